// round 12
// baseline (speedup 1.0000x reference)
#include <cuda_runtime.h>
#include <cuda_bf16.h>
#include <cuda_fp16.h>
#include <math.h>
#include <stdint.h>

// ---------------- problem constants ----------------
#define BIMG 8
#define OPI_ 64
#define RPI_ 1024
#define NN 512
#define RR 8192
#define OBJD 4096
#define HD 512
#define NOC_ 151
#define NRC_ 51
#define TSTEPS 3
#define IOU_THR_ 0.3f
#define KEMB 160

// ---------------- helpers ----------------------------------------------------
__device__ __forceinline__ void split_h(float v, __half& hi, __half& lo) {
    hi = __float2half_rn(v);
    lo = __float2half_rn(v - __half2float(hi));
}
__device__ __forceinline__ void mma_f16(float* c, const uint32_t* a, const uint32_t* b) {
    asm volatile(
        "mma.sync.aligned.m16n8k16.row.col.f32.f16.f16.f32 "
        "{%0,%1,%2,%3},{%4,%5,%6,%7},{%8,%9},{%0,%1,%2,%3};"
        : "+f"(c[0]), "+f"(c[1]), "+f"(c[2]), "+f"(c[3])
        : "r"(a[0]), "r"(a[1]), "r"(a[2]), "r"(a[3]), "r"(b[0]), "r"(b[1]));
}
__device__ __forceinline__ void cp16(uint32_t dst, const void* src) {
    asm volatile("cp.async.cg.shared.global [%0], [%1], 16;" :: "r"(dst), "l"(src));
}
#define LDSM_X4(r0, r1, r2, r3, addr) \
    asm volatile("ldmatrix.sync.aligned.m8n8.x4.shared.b16 {%0,%1,%2,%3}, [%4];" \
        : "=r"(r0), "=r"(r1), "=r"(r2), "=r"(r3) : "r"(addr))

// ---------------- f32 scratch ------------------------------------------------
__device__ float g_fo[NN * HD];
__device__ float g_h_obj[NN * HD];
__device__ float g_h_rel[RR * HD];
__device__ float g_hmhu[RR * 3 * HD];       // HM cols [0,512) used; HU fused away
__device__ float g_hw[NN * 3 * HD];         // permuted: [0,1024)=(z,r) pairs, [1024,1536)=n
__device__ float g_z_rel[RR * HD];
__device__ float g_xw_obj[NN * 3 * HD];
__device__ float g_hu_obj[NN * 2 * HD];
__device__ float g_z_obj[NN * HD];
__device__ float g_sp[NN * NOC_];
__device__ float g_wcomb[HD * 3 * HD];
__device__ float g_wcp[HD * 3 * HD];        // permuted WCOMB
__device__ float g_up[HD * 2 * HD];         // permuted U_gru_rel cols [0,1024)
__device__ float g_bcr[128];
__device__ float g_bco[256];
__device__ unsigned char g_keep[150 * NN];
__device__ int g_s_idx[RR];
__device__ int g_o_idx[RR];

// ---------------- fp16 plane scratch -----------------------------------------
__device__ __half g_Pa_h[RR * OBJD], g_Pa_l[RR * OBJD];
__device__ __half g_Pb_h[NN * OBJD], g_Pb_l[NN * OBJD];
__device__ __half g_Ps_h[RR * HD],  g_Ps_l[RR * HD];
__device__ __half g_Ph_h[RR * HD],  g_Ph_l[RR * HD];
__device__ __half g_Po1_h[NN * HD], g_Po1_l[NN * HD];
__device__ __half g_Po2_h[NN * HD], g_Po2_l[NN * HD];
__device__ __half g_Po3_h[NN * HD], g_Po3_l[NN * HD];
__device__ __half g_OP_h[NN * KEMB], g_OP_l[NN * KEMB];
// weight planes, [N,K]
__device__ __half g_Wop_h[HD * OBJD], g_Wop_l[HD * OBJD];
__device__ __half g_Wrp_h[HD * OBJD], g_Wrp_l[HD * OBJD];
__device__ __half g_Wemb_h[HD * KEMB], g_Wemb_l[HD * KEMB];
__device__ __half g_Wcb_h[3 * HD * HD], g_Wcb_l[3 * HD * HD];   // permuted WCOMB^T
__device__ __half g_Wct_h[3 * HD * HD], g_Wct_l[3 * HD * HD];   // [Wmo | perm(Ugr01)]^T
__device__ __half g_Ugr2_h[HD * HD],   g_Ugr2_l[HD * HD];
__device__ __half g_Wgo_h[3 * HD * HD], g_Wgo_l[3 * HD * HD];
__device__ __half g_Ugo_h[3 * HD * HD], g_Ugo_l[3 * HD * HD];
__device__ __half g_Wcr_h[128 * HD], g_Wcr_l[128 * HD];
__device__ __half g_Wco_h[256 * HD], g_Wco_l[256 * HD];

// ============================================================================
// fp16 3-pass GEMM body.
// mode 0: C = A@B^T (+bias) (+addm); optional planes; packN>0 -> scalar pack.
// mode 1: GRU-fin fusion (XW3 direct or gathered from HW via s/o indices).
// mode 2: HMHU + fused zr: cols<512 plain HM store; cols>=512 = (z,r)
//         interleaved pairs -> sigmoid gates, Z + RH planes.
// ============================================================================
#define HROW 20
#define HPLW (128 * HROW)
#define HSTW (4 * HPLW)
#define HG_SMEM (2 * HSTW * 4)

struct HGArgs {
    const __half *Ah, *Al, *Bh, *Bl;
    float* C; int ldc;
    int M, N, K;
    const float* bias;
    const float* addm;
    __half *Ch, *Cl;
    int mode;
    int packN;
    int gather;
    const float* XW3; int ldxw;
    const float* Z;       // mode1: read Z;  mode2: write Z (cast)
    float* Hh;            // mode1: update;  mode2: read h_rel
};

__device__ __forceinline__ void hgemm_body(const HGArgs& a, int blk) {
    extern __shared__ uint32_t sm[];
    const int tid = threadIdx.x;
    const int lane = tid & 31;
    const int warp = tid >> 5;
    const int wm = warp >> 2;
    const int wn = warp & 3;
    const int lr = lane >> 2;
    const int lc = lane & 3;
    const int nx = a.N >> 7;
    const int m0 = (blk / nx) * 128;
    const int n0 = (blk % nx) * 128;
    const int K = a.K;
    const int KT = K / 32;

    const uint32_t sbase = (uint32_t)__cvta_generic_to_shared(sm);
    const int aRowOff = (wm * 64 + (lane & 15)) * HROW + (lane >> 4) * 4;
    const int bRowOff = (wn * 32 + (lane & 7) + ((lane >> 4) << 3)) * HROW
                      + (((lane >> 3) & 1) * 4);

    const __half* Ah = a.Ah;
    const __half* Al = a.Al;
    const __half* Bh = a.Bh;
    const __half* Bl = a.Bl;

    auto load_stage = [&](int kt, int buf) {
        const int k0 = kt * 32;
        uint32_t sb = sbase + (uint32_t)(buf * HSTW * 4);
#pragma unroll
        for (int i = 0; i < 2; i++) {
            int cid = tid * 2 + i;
            int row = cid >> 2, ch = cid & 3;
            uint32_t d = sb + (uint32_t)((row * HROW + ch * 4) * 4);
            size_t src = (size_t)(m0 + row) * K + k0 + ch * 8;
            cp16(d, Ah + src);
            cp16(d + HPLW * 4, Al + src);
        }
#pragma unroll
        for (int i = 0; i < 2; i++) {
            int cid = tid * 2 + i;
            int row = cid >> 2, ch = cid & 3;
            uint32_t d = sb + (uint32_t)((2 * HPLW + row * HROW + ch * 4) * 4);
            size_t src = (size_t)(n0 + row) * K + k0 + ch * 8;
            cp16(d, Bh + src);
            cp16(d + HPLW * 4, Bl + src);
        }
        asm volatile("cp.async.commit_group;");
    };

    float acc[4][4][4];
#pragma unroll
    for (int i = 0; i < 4; i++)
#pragma unroll
        for (int j = 0; j < 4; j++)
#pragma unroll
            for (int l = 0; l < 4; l++) acc[i][j][l] = 0.f;

    load_stage(0, 0);
    if (KT > 1) load_stage(1, 1);
    asm volatile("cp.async.wait_group 1;");
    __syncthreads();

    for (int kt = 0; kt < KT; kt++) {
        const int cur = kt & 1;
        const uint32_t uA = sbase + (uint32_t)(cur * HSTW * 4);
        const uint32_t uB = uA + (uint32_t)(2 * HPLW * 4);

#pragma unroll
        for (int wc = 0; wc < 16; wc += 8) {
            uint32_t aH[4][4], aL[4][4], bH[4][2], bL[4][2];
#pragma unroll
            for (int mt = 0; mt < 4; mt++) {
                uint32_t ad = uA + (uint32_t)((aRowOff + mt * 16 * HROW + wc) * 4);
                LDSM_X4(aH[mt][0], aH[mt][1], aH[mt][2], aH[mt][3], ad);
                LDSM_X4(aL[mt][0], aL[mt][1], aL[mt][2], aL[mt][3], ad + HPLW * 4);
            }
#pragma unroll
            for (int pr = 0; pr < 2; pr++) {
                uint32_t bd = uB + (uint32_t)((bRowOff + pr * 16 * HROW + wc) * 4);
                LDSM_X4(bH[2 * pr][0], bH[2 * pr][1], bH[2 * pr + 1][0], bH[2 * pr + 1][1], bd);
                LDSM_X4(bL[2 * pr][0], bL[2 * pr][1], bL[2 * pr + 1][0], bL[2 * pr + 1][1],
                        bd + HPLW * 4);
            }
#pragma unroll
            for (int mt = 0; mt < 4; mt++)
#pragma unroll
                for (int nt = 0; nt < 4; nt++) {
                    mma_f16(acc[mt][nt], aH[mt], bH[nt]);
                    mma_f16(acc[mt][nt], aH[mt], bL[nt]);
                    mma_f16(acc[mt][nt], aL[mt], bH[nt]);
                }
        }
        __syncthreads();
        if (kt + 2 < KT) {
            load_stage(kt + 2, cur);
            asm volatile("cp.async.wait_group 1;");
        } else if (kt + 1 < KT) {
            asm volatile("cp.async.wait_group 0;");
        }
        __syncthreads();
    }

    if (a.mode == 0) {
        if (a.packN > 0) {
            // scalar pack-store directly into (possibly odd-ld) output
#pragma unroll
            for (int mt = 0; mt < 4; mt++) {
#pragma unroll
                for (int nt = 0; nt < 4; nt++) {
#pragma unroll
                    for (int v = 0; v < 4; v++) {
                        int gm = m0 + wm * 64 + mt * 16 + lr + (v >> 1) * 8;
                        int gn = n0 + wn * 32 + nt * 8 + lc * 2 + (v & 1);
                        if (gn < a.packN)
                            a.C[(size_t)gm * a.ldc + gn] = acc[mt][nt][v] + a.bias[gn];
                    }
                }
            }
        } else {
#pragma unroll
            for (int mt = 0; mt < 4; mt++) {
                int gm0 = m0 + wm * 64 + mt * 16 + lr;
                int gm1 = gm0 + 8;
#pragma unroll
                for (int nt = 0; nt < 4; nt++) {
                    int gn = n0 + wn * 32 + nt * 8 + lc * 2;
                    float b0 = 0.f, b1 = 0.f;
                    if (a.bias) { b0 = a.bias[gn]; b1 = a.bias[gn + 1]; }
                    float2 v0 = make_float2(acc[mt][nt][0] + b0, acc[mt][nt][1] + b1);
                    float2 v1 = make_float2(acc[mt][nt][2] + b0, acc[mt][nt][3] + b1);
                    if (a.addm) {
                        float2 m0v = *(const float2*)(a.addm + (size_t)gm0 * a.ldc + gn);
                        float2 m1v = *(const float2*)(a.addm + (size_t)gm1 * a.ldc + gn);
                        v0.x += m0v.x; v0.y += m0v.y;
                        v1.x += m1v.x; v1.y += m1v.y;
                    }
                    *(float2*)(a.C + (size_t)gm0 * a.ldc + gn) = v0;
                    *(float2*)(a.C + (size_t)gm1 * a.ldc + gn) = v1;
                    if (a.Ch) {
                        __half hx, lx, hy, ly;
                        split_h(v0.x, hx, lx); split_h(v0.y, hy, ly);
                        *(__half2*)(a.Ch + (size_t)gm0 * a.ldc + gn) = __halves2half2(hx, hy);
                        *(__half2*)(a.Cl + (size_t)gm0 * a.ldc + gn) = __halves2half2(lx, ly);
                        split_h(v1.x, hx, lx); split_h(v1.y, hy, ly);
                        *(__half2*)(a.Ch + (size_t)gm1 * a.ldc + gn) = __halves2half2(hx, hy);
                        *(__half2*)(a.Cl + (size_t)gm1 * a.ldc + gn) = __halves2half2(lx, ly);
                    }
                }
            }
        }
    } else if (a.mode == 1) {
        // GRU-fin: n = tanh(acc + XW3 + b); h = (1-z)h + z n
#pragma unroll
        for (int mt = 0; mt < 4; mt++) {
#pragma unroll
            for (int nt = 0; nt < 4; nt++) {
#pragma unroll
                for (int v = 0; v < 4; v++) {
                    int gm = m0 + wm * 64 + mt * 16 + lr + (v >> 1) * 8;
                    int gn = n0 + wn * 32 + nt * 8 + lc * 2 + (v & 1);
                    size_t off = (size_t)gm * a.ldc + gn;
                    float xw;
                    if (a.gather) {
                        int s = g_s_idx[gm], o = g_o_idx[gm];
                        xw = a.XW3[(size_t)s * a.ldxw + gn] + a.XW3[(size_t)o * a.ldxw + gn];
                    } else {
                        xw = a.XW3[(size_t)gm * a.ldxw + gn];
                    }
                    float n = tanhf(acc[mt][nt][v] + xw + a.bias[gn]);
                    float z = a.Z[off];
                    float h = (1.f - z) * a.Hh[off] + z * n;
                    a.Hh[off] = h;
                    __half ph, pl;
                    split_h(h, ph, pl);
                    a.Ch[off] = ph;
                    a.Cl[off] = pl;
                }
            }
        }
    } else {
        // mode 2: HMHU + fused zr. gn<512: HM store. gn>=512: (z,r) pair.
        float* Zw = (float*)a.Z;
#pragma unroll
        for (int mt = 0; mt < 4; mt++) {
            int gms[2];
            gms[0] = m0 + wm * 64 + mt * 16 + lr;
            gms[1] = gms[0] + 8;
#pragma unroll
            for (int nt = 0; nt < 4; nt++) {
                int gn = n0 + wn * 32 + nt * 8 + lc * 2;
#pragma unroll
                for (int p = 0; p < 2; p++) {
                    int gm = gms[p];
                    float vx = acc[mt][nt][2 * p];
                    float vy = acc[mt][nt][2 * p + 1];
                    if (gn < 512) {
                        *(float2*)(a.C + (size_t)gm * a.ldc + gn) = make_float2(vx, vy);
                    } else {
                        int q = gn - 512;       // even; z col q, r col q+1 in HW
                        int c = q >> 1;
                        int s = g_s_idx[gm], o = g_o_idx[gm];
                        float zp = vx + a.XW3[(size_t)s * a.ldxw + q]
                                      + a.XW3[(size_t)o * a.ldxw + q] + a.bias[c];
                        float rp = vy + a.XW3[(size_t)s * a.ldxw + q + 1]
                                      + a.XW3[(size_t)o * a.ldxw + q + 1] + a.bias[512 + c];
                        float z = 1.f / (1.f + expf(-zp));
                        float r = 1.f / (1.f + expf(-rp));
                        size_t off = (size_t)gm * HD + c;
                        Zw[off] = z;
                        __half ph, pl;
                        split_h(r * a.Hh[off], ph, pl);
                        a.Ch[off] = ph;
                        a.Cl[off] = pl;
                    }
                }
            }
        }
    }
}

__global__ __launch_bounds__(256, 2) void hgemm_kernel(HGArgs a) {
    hgemm_body(a, blockIdx.x);
}
__global__ __launch_bounds__(256, 2) void hgemm_dual_kernel(HGArgs a, HGArgs b, int na) {
    int bx = blockIdx.x;
    if (bx < na) hgemm_body(a, bx);
    else hgemm_body(b, bx - na);
}

// ---------------- split / perm kernels ----------------------------------------
__global__ void asplit_kernel(const float2* __restrict__ in,
                              __half2* __restrict__ hi, __half2* __restrict__ lo, int n2) {
    int i = blockIdx.x * blockDim.x + threadIdx.x;
    if (i >= n2) return;
    float2 v = in[i];
    __half hx, lx, hy, ly;
    split_h(v.x, hx, lx);
    split_h(v.y, hy, ly);
    hi[i] = __halves2half2(hx, hy);
    lo[i] = __halves2half2(lx, ly);
}

__global__ void wsplit_kernel(const float* __restrict__ W, int ldw, int c0, int wcols, int wrows,
                              __half* __restrict__ Th, __half* __restrict__ Tl, int K) {
    __shared__ float t[32][33];
    int kb = blockIdx.y * 32, nb = blockIdx.x * 32;
    int tx = threadIdx.x, ty = threadIdx.y;
    int col = c0 + nb + tx;
#pragma unroll
    for (int i = 0; i < 32; i += 8) {
        int kr = kb + ty + i;
        t[ty + i][tx] = (col < wcols && kr < wrows) ? W[(size_t)kr * ldw + col] : 0.f;
    }
    __syncthreads();
#pragma unroll
    for (int i = 0; i < 32; i += 8) {
        int n = nb + ty + i, k = kb + tx;
        __half h, l;
        split_h(t[tx][ty + i], h, l);
        Th[(size_t)n * K + k] = h;
        Tl[(size_t)n * K + k] = l;
    }
}

// dst[k][p] = src[k][orig(p)]; orig(p) = p<2*npair ? ((p&1)? npair+(p>>1) : (p>>1)) : p
__global__ void colperm_kernel(const float* __restrict__ src, int lds,
                               float* __restrict__ dst, int ldd,
                               int rows, int ncols, int npair) {
    int i = blockIdx.x * blockDim.x + threadIdx.x;
    if (i >= rows * ncols) return;
    int k = i / ncols, p = i % ncols;
    int orig = (p < 2 * npair) ? (((p & 1) ? npair : 0) + (p >> 1)) : p;
    dst[(size_t)k * ldd + p] = src[(size_t)k * lds + orig];
}

__global__ void biaspad_kernel(const float* __restrict__ b, float* __restrict__ out,
                               int n, int npad) {
    int i = blockIdx.x * blockDim.x + threadIdx.x;
    if (i < npad) out[i] = (i < n) ? b[i] : 0.f;
}

// ---------------- generic fp32 SGEMM (WCOMB only) ------------------------------
__global__ __launch_bounds__(256) void sgemm_kernel(
    const float* __restrict__ A, int lda,
    const float* __restrict__ B, int ldb,
    float* __restrict__ C, int ldc,
    int M, int N, int K)
{
    __shared__ float As[8][132];
    __shared__ float Bs[8][128];
    const int tid = threadIdx.x;
    const int tx = tid & 15;
    const int ty = tid >> 4;
    const int m0 = blockIdx.y * 128;
    const int n0 = blockIdx.x * 128;

    float acc[8][8];
#pragma unroll
    for (int i = 0; i < 8; i++)
#pragma unroll
        for (int j = 0; j < 8; j++) acc[i][j] = 0.f;

    for (int k0 = 0; k0 < K; k0 += 8) {
#pragma unroll
        for (int l = 0; l < 4; l++) {
            int e = tid + l * 256;
            int r = e >> 3, c = e & 7;
            float v = 0.f;
            int gm = m0 + r, gk = k0 + c;
            if (gm < M && gk < K) v = A[(size_t)gm * lda + gk];
            As[c][r] = v;
        }
#pragma unroll
        for (int l = 0; l < 4; l++) {
            int e = tid + l * 256;
            int r = e >> 7, c = e & 127;
            float v = 0.f;
            int gk = k0 + r, gn = n0 + c;
            if (gk < K && gn < N) v = B[(size_t)gk * ldb + gn];
            Bs[r][c] = v;
        }
        __syncthreads();
#pragma unroll
        for (int k = 0; k < 8; k++) {
            float a[8], b[8];
#pragma unroll
            for (int i = 0; i < 8; i++) a[i] = As[k][ty * 8 + i];
#pragma unroll
            for (int j = 0; j < 8; j++) b[j] = Bs[k][tx * 8 + j];
#pragma unroll
            for (int i = 0; i < 8; i++)
#pragma unroll
                for (int j = 0; j < 8; j++)
                    acc[i][j] = fmaf(a[i], b[j], acc[i][j]);
        }
        __syncthreads();
    }
#pragma unroll
    for (int i = 0; i < 8; i++) {
        int gm = m0 + ty * 8 + i;
        if (gm >= M) continue;
#pragma unroll
        for (int j = 0; j < 8; j++) {
            int gn = n0 + tx * 8 + j;
            if (gn >= N) continue;
            C[(size_t)gm * ldc + gn] = acc[i][j];
        }
    }
}

// ---------------- decode rel_inds ----------------------------------------------
__global__ __launch_bounds__(1024) void decode_rel_kernel(const void* rel_raw) {
    __shared__ int s_or;
    int tid = threadIdx.x;
    if (tid == 0) s_or = 0;
    __syncthreads();
    const int* v32 = (const int*)rel_raw;
    int acc = 0;
    for (int i = tid; i < (3 * RR) / 2; i += 1024) acc |= v32[2 * i + 1];
    if (acc) atomicOr(&s_or, 1);
    __syncthreads();
    bool is64 = (s_or == 0);
    if (is64) {
        const long long* v = (const long long*)rel_raw;
        for (int r = tid; r < RR; r += 1024) {
            g_s_idx[r] = (int)v[3 * r + 1];
            g_o_idx[r] = (int)v[3 * r + 2];
        }
    } else {
        for (int r = tid; r < RR; r += 1024) {
            g_s_idx[r] = v32[3 * r + 1];
            g_o_idx[r] = v32[3 * r + 2];
        }
    }
}

// ---------------- softmax -> padded fp16 planes ---------------------------------
__global__ void softmax_split_kernel(const float* __restrict__ X,
                                     __half* __restrict__ Ph, __half* __restrict__ Pl) {
    int row = blockIdx.x;
    int tid = threadIdx.x;
    __shared__ float red[256];
    const float* x = X + (size_t)row * NOC_;
    float m = -3.4e38f;
    for (int c = tid; c < NOC_; c += 256) m = fmaxf(m, x[c]);
    red[tid] = m; __syncthreads();
    for (int s = 128; s > 0; s >>= 1) {
        if (tid < s) red[tid] = fmaxf(red[tid], red[tid + s]);
        __syncthreads();
    }
    m = red[0]; __syncthreads();
    float sum = 0.f;
    for (int c = tid; c < NOC_; c += 256) sum += expf(x[c] - m);
    red[tid] = sum; __syncthreads();
    for (int s = 128; s > 0; s >>= 1) {
        if (tid < s) red[tid] += red[tid + s];
        __syncthreads();
    }
    float inv = 1.f / red[0];
    for (int c = tid; c < KEMB; c += 256) {
        float v = (c < NOC_) ? expf(x[c] - m) * inv : 0.f;
        __half h, l;
        split_h(v, h, l);
        Ph[(size_t)row * KEMB + c] = h;
        Pl[(size_t)row * KEMB + c] = l;
    }
}

__global__ void softmax_kernel(const float* __restrict__ X, float* __restrict__ Y) {
    int row = blockIdx.x;
    int tid = threadIdx.x;
    __shared__ float red[256];
    const float* x = X + (size_t)row * NOC_;
    float m = -3.4e38f;
    for (int c = tid; c < NOC_; c += 256) m = fmaxf(m, x[c]);
    red[tid] = m; __syncthreads();
    for (int s = 128; s > 0; s >>= 1) {
        if (tid < s) red[tid] = fmaxf(red[tid], red[tid + s]);
        __syncthreads();
    }
    m = red[0]; __syncthreads();
    float sum = 0.f;
    for (int c = tid; c < NOC_; c += 256) sum += expf(x[c] - m);
    red[tid] = sum; __syncthreads();
    for (int s = 128; s > 0; s >>= 1) {
        if (tid < s) red[tid] += red[tid + s];
        __syncthreads();
    }
    float inv = 1.f / red[0];
    for (int c = tid; c < NOC_; c += 256)
        Y[(size_t)row * NOC_ + c] = expf(x[c] - m) * inv;
}

// ---------------- m_obj scatter -> planes ---------------------------------------
__global__ __launch_bounds__(512) void scatter_obj_kernel(const float* __restrict__ HM, int ldhm,
                                                          __half* __restrict__ Mh,
                                                          __half* __restrict__ Ml) {
    int obj = blockIdx.x;
    int c = threadIdx.x;
    int img = obj >> 6;
    int base = img * RPI_;
    __shared__ int ss[RPI_];
    __shared__ int oo[RPI_];
    for (int j = c; j < RPI_; j += 512) {
        ss[j] = g_s_idx[base + j];
        oo[j] = g_o_idx[base + j];
    }
    __syncthreads();
    float acc = 0.f;
    for (int j = 0; j < RPI_; j++) {
        if (ss[j] == obj) acc += HM[(size_t)(base + j) * ldhm + c];
        if (oo[j] == obj) acc += HM[(size_t)(base + j) * ldhm + c];
    }
    __half h, l;
    split_h(acc, h, l);
    Mh[(size_t)obj * HD + c] = h;
    Ml[(size_t)obj * HD + c] = l;
}

// ---------------- GRU z, r*h (obj path) ------------------------------------------
__global__ void gru_zr_kernel(const float* __restrict__ XW, int ldxw,
                              const float* __restrict__ HU, int ldhu,
                              const float* __restrict__ b, const float* __restrict__ Hh,
                              float* __restrict__ Z,
                              __half* __restrict__ RHh, __half* __restrict__ RHl, int M) {
    int idx = blockIdx.x * blockDim.x + threadIdx.x;
    if (idx >= M * HD) return;
    int row = idx >> 9;
    int c = idx & 511;
    float z = XW[(size_t)row * ldxw + c] + HU[(size_t)row * ldhu + c] + b[c];
    float r = XW[(size_t)row * ldxw + 512 + c] + HU[(size_t)row * ldhu + 512 + c] + b[512 + c];
    z = 1.f / (1.f + expf(-z));
    r = 1.f / (1.f + expf(-r));
    Z[idx] = z;
    __half h, l;
    split_h(r * Hh[idx], h, l);
    RHh[idx] = h; RHl[idx] = l;
}

// ---------------- NMS -------------------------------------------------------------
__global__ __launch_bounds__(512) void nms_kernel(const float* __restrict__ SP,
                                                  const float* __restrict__ BOX,
                                                  unsigned char* __restrict__ KEEP) {
    int cls = blockIdx.x + 1;
    int tid = threadIdx.x;
    __shared__ float sc[NN];
    __shared__ int sidx[NN];
    __shared__ float bx[NN][4];
    __shared__ float area[NN];
    __shared__ unsigned char keep[NN];

    sc[tid] = SP[(size_t)tid * NOC_ + cls];
    sidx[tid] = tid;
    __syncthreads();

    for (int k = 2; k <= NN; k <<= 1) {
        for (int j = k >> 1; j > 0; j >>= 1) {
            int ixj = tid ^ j;
            if (ixj > tid) {
                float s1 = sc[tid], s2 = sc[ixj];
                int i1 = sidx[tid], i2 = sidx[ixj];
                bool dir = ((tid & k) == 0);
                bool precBA = (s2 > s1) || (s2 == s1 && i2 < i1);
                if (precBA == dir) {
                    sc[tid] = s2; sc[ixj] = s1;
                    sidx[tid] = i2; sidx[ixj] = i1;
                }
            }
            __syncthreads();
        }
    }

    int oi = sidx[tid];
    float x1 = BOX[((size_t)oi * NOC_ + cls) * 4 + 0];
    float y1 = BOX[((size_t)oi * NOC_ + cls) * 4 + 1];
    float x2 = BOX[((size_t)oi * NOC_ + cls) * 4 + 2];
    float y2 = BOX[((size_t)oi * NOC_ + cls) * 4 + 3];
    bx[tid][0] = x1; bx[tid][1] = y1; bx[tid][2] = x2; bx[tid][3] = y2;
    area[tid] = (x2 - x1) * (y2 - y1);
    keep[tid] = 1;
    __syncthreads();

    for (int i = 0; i < NN - 1; i++) {
        if (tid > i && keep[i] && keep[tid]) {
            float lx = fmaxf(bx[i][0], x1);
            float ly = fmaxf(bx[i][1], y1);
            float rx = fminf(bx[i][2], x2);
            float ry = fminf(bx[i][3], y2);
            float w = fmaxf(rx - lx, 0.f);
            float h = fmaxf(ry - ly, 0.f);
            float inter = w * h;
            float iou = inter / (area[i] + area[tid] - inter + 1e-9f);
            if (iou > IOU_THR_) keep[tid] = 0;
        }
        __syncthreads();
    }
    KEEP[(size_t)(cls - 1) * NN + oi] = keep[tid];
}

__global__ void preds_kernel(const float* __restrict__ SP, const unsigned char* __restrict__ KEEP,
                             float* __restrict__ out) {
    int n = blockIdx.x * blockDim.x + threadIdx.x;
    if (n >= NN) return;
    float best = -1.f;
    int bi = 0;
    for (int c = 0; c < 150; c++) {
        float v = KEEP[(size_t)c * NN + n] ? SP[(size_t)n * NOC_ + c + 1] : 0.f;
        if (v > best) { best = v; bi = c; }
    }
    out[n] = (float)(bi + 1);
}

// ---------------- host orchestration ----------------------------------------------
struct Scratch {
    float *FO, *HOBJ, *HREL, *HMHU, *HW, *ZR;
    float *XWO, *HUO, *ZO, *SP, *WCOMB, *WCP, *UP, *BCR, *BCO;
    unsigned char* KEEP;
    __half *Pa_h, *Pa_l, *Pb_h, *Pb_l, *Ps_h, *Ps_l, *Ph_h, *Ph_l;
    __half *Po1_h, *Po1_l, *Po2_h, *Po2_l, *Po3_h, *Po3_l, *OP_h, *OP_l;
    __half *Wop_h, *Wop_l, *Wrp_h, *Wrp_l, *Wemb_h, *Wemb_l;
    __half *Wcb_h, *Wcb_l, *Wct_h, *Wct_l;
    __half *Ugr2_h, *Ugr2_l, *Wgo_h, *Wgo_l, *Ugo_h, *Ugo_l;
    __half *Wcr_h, *Wcr_l, *Wco_h, *Wco_l;
    bool init = false;
};
static Scratch g_sc;

static void init_scratch() {
    if (g_sc.init) return;
    void* p;
#define GET(sym, fld, T) cudaGetSymbolAddress(&p, sym); g_sc.fld = (T*)p;
    GET(g_fo, FO, float)
    GET(g_h_obj, HOBJ, float)
    GET(g_h_rel, HREL, float)
    GET(g_hmhu, HMHU, float)
    GET(g_hw, HW, float)
    GET(g_z_rel, ZR, float)
    GET(g_xw_obj, XWO, float)
    GET(g_hu_obj, HUO, float)
    GET(g_z_obj, ZO, float)
    GET(g_sp, SP, float)
    GET(g_wcomb, WCOMB, float)
    GET(g_wcp, WCP, float)
    GET(g_up, UP, float)
    GET(g_bcr, BCR, float)
    GET(g_bco, BCO, float)
    GET(g_keep, KEEP, unsigned char)
    GET(g_Pa_h, Pa_h, __half) GET(g_Pa_l, Pa_l, __half)
    GET(g_Pb_h, Pb_h, __half) GET(g_Pb_l, Pb_l, __half)
    GET(g_Ps_h, Ps_h, __half) GET(g_Ps_l, Ps_l, __half)
    GET(g_Ph_h, Ph_h, __half) GET(g_Ph_l, Ph_l, __half)
    GET(g_Po1_h, Po1_h, __half) GET(g_Po1_l, Po1_l, __half)
    GET(g_Po2_h, Po2_h, __half) GET(g_Po2_l, Po2_l, __half)
    GET(g_Po3_h, Po3_h, __half) GET(g_Po3_l, Po3_l, __half)
    GET(g_OP_h, OP_h, __half)  GET(g_OP_l, OP_l, __half)
    GET(g_Wop_h, Wop_h, __half) GET(g_Wop_l, Wop_l, __half)
    GET(g_Wrp_h, Wrp_h, __half) GET(g_Wrp_l, Wrp_l, __half)
    GET(g_Wemb_h, Wemb_h, __half) GET(g_Wemb_l, Wemb_l, __half)
    GET(g_Wcb_h, Wcb_h, __half) GET(g_Wcb_l, Wcb_l, __half)
    GET(g_Wct_h, Wct_h, __half) GET(g_Wct_l, Wct_l, __half)
    GET(g_Ugr2_h, Ugr2_h, __half) GET(g_Ugr2_l, Ugr2_l, __half)
    GET(g_Wgo_h, Wgo_h, __half) GET(g_Wgo_l, Wgo_l, __half)
    GET(g_Ugo_h, Ugo_h, __half) GET(g_Ugo_l, Ugo_l, __half)
    GET(g_Wcr_h, Wcr_h, __half) GET(g_Wcr_l, Wcr_l, __half)
    GET(g_Wco_h, Wco_h, __half) GET(g_Wco_l, Wco_l, __half)
#undef GET
    cudaFuncSetAttribute(hgemm_kernel, cudaFuncAttributeMaxDynamicSharedMemorySize, HG_SMEM);
    cudaFuncSetAttribute(hgemm_dual_kernel, cudaFuncAttributeMaxDynamicSharedMemorySize, HG_SMEM);
    g_sc.init = true;
}

static HGArgs mkargs(const __half* Ah, const __half* Al, const __half* Bh, const __half* Bl,
                     float* C, int ldc, int M, int N, int K, const float* bias,
                     __half* Ch = nullptr, __half* Cl = nullptr) {
    HGArgs a;
    a.Ah = Ah; a.Al = Al; a.Bh = Bh; a.Bl = Bl;
    a.C = C; a.ldc = ldc; a.M = M; a.N = N; a.K = K;
    a.bias = bias; a.addm = nullptr; a.Ch = Ch; a.Cl = Cl;
    a.mode = 0; a.packN = 0; a.gather = 0;
    a.XW3 = nullptr; a.ldxw = 0; a.Z = nullptr; a.Hh = nullptr;
    return a;
}

static int nblk(const HGArgs& a) { return (a.M / 128) * (a.N / 128); }
static void hgemm1(const HGArgs& a) {
    hgemm_kernel<<<nblk(a), 256, HG_SMEM>>>(a);
}
static void hgemm2(const HGArgs& a, const HGArgs& b) {
    hgemm_dual_kernel<<<nblk(a) + nblk(b), 256, HG_SMEM>>>(a, b, nblk(a));
}

static void asplit(const float* A, __half* hi, __half* lo, int n) {
    int n2 = n / 2;
    asplit_kernel<<<(n2 + 255) / 256, 256>>>((const float2*)A, (__half2*)hi, (__half2*)lo, n2);
}

static void wsplit(const float* W, int ldw, int c0, int wcols, int wrows,
                   __half* Th, __half* Tl, int K, int ncols) {
    dim3 g(ncols / 32, K / 32);
    wsplit_kernel<<<g, dim3(32, 8)>>>(W, ldw, c0, wcols, wrows, Th, Tl, K);
}

extern "C" void kernel_launch(void* const* d_in, const int* in_sizes, int n_in,
                              void* d_out, int out_size) {
    (void)in_sizes; (void)n_in; (void)out_size;
    init_scratch();

    const float* obj_fmaps  = (const float*)d_in[1];
    const float* obj_logits = (const float*)d_in[2];
    const void*  rel_raw    = d_in[3];
    const float* vr         = (const float*)d_in[4];
    const float* boxes      = (const float*)d_in[5];
    const float* W_obj_proj = (const float*)d_in[6];
    const float* b_obj_proj = (const float*)d_in[7];
    const float* W_rel_proj = (const float*)d_in[8];
    const float* b_rel_proj = (const float*)d_in[9];
    const float* W_emb      = (const float*)d_in[10];
    const float* W_msg_rel  = (const float*)d_in[11];
    const float* W_msg_obj  = (const float*)d_in[12];
    const float* W_gru_obj  = (const float*)d_in[13];
    const float* U_gru_obj  = (const float*)d_in[14];
    const float* b_gru_obj  = (const float*)d_in[15];
    const float* W_gru_rel  = (const float*)d_in[16];
    const float* U_gru_rel  = (const float*)d_in[17];
    const float* b_gru_rel  = (const float*)d_in[18];
    const float* W_cls_rel  = (const float*)d_in[19];
    const float* b_cls_rel  = (const float*)d_in[20];
    const float* W_cls_obj  = (const float*)d_in[21];
    const float* b_cls_obj  = (const float*)d_in[22];

    float* out_obj_logits = (float*)d_out;
    float* out_preds      = out_obj_logits + NN * NOC_;
    float* out_rel_logits = out_preds + NN;

    // 0. decode; weight planes
    decode_rel_kernel<<<1, 1024>>>(rel_raw);
    wsplit(W_obj_proj, HD, 0, HD, OBJD, g_sc.Wop_h, g_sc.Wop_l, OBJD, HD);
    wsplit(W_rel_proj, HD, 0, HD, OBJD, g_sc.Wrp_h, g_sc.Wrp_l, OBJD, HD);
    wsplit(W_emb, HD, 0, HD, NOC_, g_sc.Wemb_h, g_sc.Wemb_l, KEMB, HD);
    // WCAT: rows 0-511 = W_msg_obj^T; rows 512-1535 = perm(U_gru_rel[:, :1024])^T
    wsplit(W_msg_obj, HD, 0, HD, HD, g_sc.Wct_h, g_sc.Wct_l, HD, HD);
    colperm_kernel<<<(HD * 2 * HD + 255) / 256, 256>>>(U_gru_rel, 3 * HD, g_sc.UP, 2 * HD,
                                                        HD, 2 * HD, HD);
    wsplit(g_sc.UP, 2 * HD, 0, 2 * HD, HD, g_sc.Wct_h + (size_t)HD * HD,
           g_sc.Wct_l + (size_t)HD * HD, HD, 2 * HD);
    wsplit(U_gru_rel, 3 * HD, 2 * HD, 3 * HD, HD, g_sc.Ugr2_h, g_sc.Ugr2_l, HD, HD);
    wsplit(W_gru_obj, 3 * HD, 0, 3 * HD, HD, g_sc.Wgo_h, g_sc.Wgo_l, HD, 3 * HD);
    wsplit(U_gru_obj, 3 * HD, 0, 3 * HD, HD, g_sc.Ugo_h, g_sc.Ugo_l, HD, 3 * HD);
    wsplit(W_cls_rel, NRC_, 0, NRC_, HD, g_sc.Wcr_h, g_sc.Wcr_l, HD, 128);
    wsplit(W_cls_obj, NOC_, 0, NOC_, HD, g_sc.Wco_h, g_sc.Wco_l, HD, 256);
    biaspad_kernel<<<1, 128>>>(b_cls_rel, g_sc.BCR, NRC_, 128);
    biaspad_kernel<<<1, 256>>>(b_cls_obj, g_sc.BCO, NOC_, 256);
    // WCOMB = W_msg_rel @ W_gru_rel (f32), permute cols, planes
    {
        dim3 g((3 * HD + 127) / 128, (HD + 127) / 128);
        sgemm_kernel<<<g, 256>>>(W_msg_rel, HD, W_gru_rel, 3 * HD, g_sc.WCOMB, 3 * HD,
                                 HD, 3 * HD, HD);
    }
    colperm_kernel<<<(HD * 3 * HD + 255) / 256, 256>>>(g_sc.WCOMB, 3 * HD, g_sc.WCP, 3 * HD,
                                                        HD, 3 * HD, HD);
    wsplit(g_sc.WCP, 3 * HD, 0, 3 * HD, HD, g_sc.Wcb_h, g_sc.Wcb_l, HD, 3 * HD);

    // 1. activation splits
    asplit(obj_fmaps, g_sc.Pb_h, g_sc.Pb_l, NN * OBJD);
    asplit(vr, g_sc.Pa_h, g_sc.Pa_l, RR * OBJD);
    softmax_split_kernel<<<NN, 256>>>(obj_logits, g_sc.OP_h, g_sc.OP_l);

    // 2. fo + h_rel (paired)
    hgemm2(mkargs(g_sc.Pb_h, g_sc.Pb_l, g_sc.Wop_h, g_sc.Wop_l, g_sc.FO, HD,
                  NN, HD, OBJD, b_obj_proj),
           mkargs(g_sc.Pa_h, g_sc.Pa_l, g_sc.Wrp_h, g_sc.Wrp_l, g_sc.HREL, HD,
                  RR, HD, OBJD, b_rel_proj, g_sc.Ph_h, g_sc.Ph_l));

    // 3. h_obj = obj_probs @ W_emb + fo
    {
        HGArgs a = mkargs(g_sc.OP_h, g_sc.OP_l, g_sc.Wemb_h, g_sc.Wemb_l, g_sc.HOBJ, HD,
                          NN, HD, KEMB, nullptr, g_sc.Po2_h, g_sc.Po2_l);
        a.addm = g_sc.FO;
        hgemm1(a);
    }

    const int EW_OBJ = (NN * HD + 255) / 256;
    const __half* Ugo2_h = g_sc.Ugo_h + (size_t)2 * HD * HD;
    const __half* Ugo2_l = g_sc.Ugo_l + (size_t)2 * HD * HD;

    for (int t = 0; t < TSTEPS; t++) {
        // (a) HW = HOBJ@WCOMB_perm  +  HUO = HOBJ@Ugo01   (dual; HW needed by (b))
        hgemm2(mkargs(g_sc.Po2_h, g_sc.Po2_l, g_sc.Wcb_h, g_sc.Wcb_l, g_sc.HW, 3 * HD,
                      NN, 3 * HD, HD, nullptr),
               mkargs(g_sc.Po2_h, g_sc.Po2_l, g_sc.Ugo_h, g_sc.Ugo_l, g_sc.HUO, 2 * HD,
                      NN, 2 * HD, HD, nullptr));

        // (b) HMHU = h_rel@WCAT_perm with fused zr epilogue
        {
            HGArgs a = mkargs(g_sc.Ph_h, g_sc.Ph_l, g_sc.Wct_h, g_sc.Wct_l, g_sc.HMHU, 3 * HD,
                              RR, 3 * HD, HD, b_gru_rel, g_sc.Ps_h, g_sc.Ps_l);
            a.mode = 2;
            a.XW3 = g_sc.HW; a.ldxw = 3 * HD;
            a.Z = g_sc.ZR; a.Hh = g_sc.HREL;
            hgemm1(a);
        }
        scatter_obj_kernel<<<NN, 512>>>(g_sc.HMHU, 3 * HD, g_sc.Po1_h, g_sc.Po1_l);

        // (c) rel fin (gathered XW3 from HW n-part) + XWO dual
        {
            HGArgs fin = mkargs(g_sc.Ps_h, g_sc.Ps_l, g_sc.Ugr2_h, g_sc.Ugr2_l,
                                nullptr, HD, RR, HD, HD, b_gru_rel + 2 * HD,
                                g_sc.Ph_h, g_sc.Ph_l);
            fin.mode = 1; fin.gather = 1;
            fin.XW3 = g_sc.HW + 2 * HD; fin.ldxw = 3 * HD;
            fin.Z = g_sc.ZR; fin.Hh = g_sc.HREL;
            hgemm2(fin,
                   mkargs(g_sc.Po1_h, g_sc.Po1_l, g_sc.Wgo_h, g_sc.Wgo_l, g_sc.XWO, 3 * HD,
                          NN, 3 * HD, HD, nullptr));
        }

        // (d) obj zr + fin
        gru_zr_kernel<<<EW_OBJ, 256>>>(g_sc.XWO, 3 * HD, g_sc.HUO, 2 * HD,
                                       b_gru_obj, g_sc.HOBJ, g_sc.ZO, g_sc.Po3_h, g_sc.Po3_l, NN);
        {
            HGArgs fin = mkargs(g_sc.Po3_h, g_sc.Po3_l, Ugo2_h, Ugo2_l,
                                nullptr, HD, NN, HD, HD, b_gru_obj + 2 * HD,
                                g_sc.Po2_h, g_sc.Po2_l);
            fin.mode = 1;
            fin.XW3 = g_sc.XWO + 2 * HD; fin.ldxw = 3 * HD;
            fin.Z = g_sc.ZO; fin.Hh = g_sc.HOBJ;
            hgemm1(fin);
        }
    }

    // classifiers write straight into d_out (packN scalar stores)
    {
        HGArgs rc = mkargs(g_sc.Ph_h, g_sc.Ph_l, g_sc.Wcr_h, g_sc.Wcr_l,
                           out_rel_logits, NRC_, RR, 128, HD, g_sc.BCR);
        rc.packN = NRC_;
        HGArgs oc = mkargs(g_sc.Po2_h, g_sc.Po2_l, g_sc.Wco_h, g_sc.Wco_l,
                           out_obj_logits, NOC_, NN, 256, HD, g_sc.BCO);
        oc.packN = NOC_;
        hgemm2(rc, oc);
    }

    // softmax -> NMS -> preds
    softmax_kernel<<<NN, 256>>>(out_obj_logits, g_sc.SP);
    nms_kernel<<<150, 512>>>(g_sc.SP, boxes, g_sc.KEEP);
    preds_kernel<<<(NN + 255) / 256, 256>>>(g_sc.SP, g_sc.KEEP, out_preds);
}

// round 13
// speedup vs baseline: 1.0648x; 1.0648x over previous
#include <cuda_runtime.h>
#include <cuda_bf16.h>
#include <cuda_fp16.h>
#include <math.h>
#include <stdint.h>

// ---------------- problem constants ----------------
#define BIMG 8
#define OPI_ 64
#define RPI_ 1024
#define NN 512
#define RR 8192
#define OBJD 4096
#define HD 512
#define NOC_ 151
#define NRC_ 51
#define TSTEPS 3
#define IOU_THR_ 0.3f
#define KEMB 160

// ---------------- helpers ----------------------------------------------------
__device__ __forceinline__ void split_h(float v, __half& hi, __half& lo) {
    hi = __float2half_rn(v);
    lo = __float2half_rn(v - __half2float(hi));
}
__device__ __forceinline__ void mma_f16(float* c, const uint32_t* a, const uint32_t* b) {
    asm volatile(
        "mma.sync.aligned.m16n8k16.row.col.f32.f16.f16.f32 "
        "{%0,%1,%2,%3},{%4,%5,%6,%7},{%8,%9},{%0,%1,%2,%3};"
        : "+f"(c[0]), "+f"(c[1]), "+f"(c[2]), "+f"(c[3])
        : "r"(a[0]), "r"(a[1]), "r"(a[2]), "r"(a[3]), "r"(b[0]), "r"(b[1]));
}
__device__ __forceinline__ void cp16(uint32_t dst, const void* src) {
    asm volatile("cp.async.cg.shared.global [%0], [%1], 16;" :: "r"(dst), "l"(src));
}
#define LDSM_X4(r0, r1, r2, r3, addr) \
    asm volatile("ldmatrix.sync.aligned.m8n8.x4.shared.b16 {%0,%1,%2,%3}, [%4];" \
        : "=r"(r0), "=r"(r1), "=r"(r2), "=r"(r3) : "r"(addr))

// ---------------- f32 scratch ------------------------------------------------
__device__ float g_fo[NN * HD];
__device__ float g_h_obj[NN * HD];
__device__ float g_h_rel[RR * HD];
__device__ float g_xw_rel[RR * 3 * HD];
__device__ float g_hmhu[RR * 3 * HD];
__device__ float g_hw[NN * 3 * HD];
__device__ float g_z_rel[RR * HD];
__device__ float g_xw_obj[NN * 3 * HD];
__device__ float g_hu_obj[NN * 2 * HD];
__device__ float g_z_obj[NN * HD];
__device__ float g_sp[NN * NOC_];
__device__ float g_wcomb[HD * 3 * HD];
__device__ float g_bcr[128];
__device__ float g_bco[256];
__device__ unsigned char g_keep[150 * NN];
__device__ int g_s_idx[RR];
__device__ int g_o_idx[RR];

// ---------------- fp16 plane scratch -----------------------------------------
__device__ __half g_Pa_h[RR * OBJD], g_Pa_l[RR * OBJD];
__device__ __half g_Pb_h[NN * OBJD], g_Pb_l[NN * OBJD];
__device__ __half g_Ps_h[RR * HD],  g_Ps_l[RR * HD];
__device__ __half g_Ph_h[RR * HD],  g_Ph_l[RR * HD];
__device__ __half g_Po1_h[NN * HD], g_Po1_l[NN * HD];
__device__ __half g_Po2_h[NN * HD], g_Po2_l[NN * HD];
__device__ __half g_Po3_h[NN * HD], g_Po3_l[NN * HD];
__device__ __half g_OP_h[NN * KEMB], g_OP_l[NN * KEMB];
// weight planes, [N,K]
__device__ __half g_Wop_h[HD * OBJD], g_Wop_l[HD * OBJD];
__device__ __half g_Wrp_h[HD * OBJD], g_Wrp_l[HD * OBJD];
__device__ __half g_Wemb_h[HD * KEMB], g_Wemb_l[HD * KEMB];
__device__ __half g_Wcb_h[3 * HD * HD], g_Wcb_l[3 * HD * HD];
__device__ __half g_Wct_h[3 * HD * HD], g_Wct_l[3 * HD * HD];
__device__ __half g_Ugr2_h[HD * HD],   g_Ugr2_l[HD * HD];
__device__ __half g_Wgo_h[3 * HD * HD], g_Wgo_l[3 * HD * HD];
__device__ __half g_Ugo_h[3 * HD * HD], g_Ugo_l[3 * HD * HD];
__device__ __half g_Wcr_h[128 * HD], g_Wcr_l[128 * HD];
__device__ __half g_Wco_h[256 * HD], g_Wco_l[256 * HD];

// ============================================================================
// fp16 3-pass GEMM body (hi/lo planes), ldmatrix fragments.
// mode 0: C = A@B^T (+bias) (+addm); optional planes; packN>0 -> scalar pack.
// mode 1: GRU-fin fusion (contiguous XW3 only).
// ============================================================================
#define HROW 20
#define HPLW (128 * HROW)
#define HSTW (4 * HPLW)
#define HG_SMEM (2 * HSTW * 4)

struct HGArgs {
    const __half *Ah, *Al, *Bh, *Bl;
    float* C; int ldc;
    int M, N, K;
    const float* bias;
    const float* addm;
    __half *Ch, *Cl;
    int mode;
    int packN;
    const float* XW3; int ldxw;
    const float* Z;
    float* Hh;
};

__device__ __forceinline__ void hgemm_body(const HGArgs& a, int blk) {
    extern __shared__ uint32_t sm[];
    const int tid = threadIdx.x;
    const int lane = tid & 31;
    const int warp = tid >> 5;
    const int wm = warp >> 2;
    const int wn = warp & 3;
    const int lr = lane >> 2;
    const int lc = lane & 3;
    const int nx = a.N >> 7;
    const int m0 = (blk / nx) * 128;
    const int n0 = (blk % nx) * 128;
    const int K = a.K;
    const int KT = K / 32;

    const uint32_t sbase = (uint32_t)__cvta_generic_to_shared(sm);
    const int aRowOff = (wm * 64 + (lane & 15)) * HROW + (lane >> 4) * 4;
    const int bRowOff = (wn * 32 + (lane & 7) + ((lane >> 4) << 3)) * HROW
                      + (((lane >> 3) & 1) * 4);

    const __half* Ah = a.Ah;
    const __half* Al = a.Al;
    const __half* Bh = a.Bh;
    const __half* Bl = a.Bl;

    auto load_stage = [&](int kt, int buf) {
        const int k0 = kt * 32;
        uint32_t sb = sbase + (uint32_t)(buf * HSTW * 4);
#pragma unroll
        for (int i = 0; i < 2; i++) {
            int cid = tid * 2 + i;
            int row = cid >> 2, ch = cid & 3;
            uint32_t d = sb + (uint32_t)((row * HROW + ch * 4) * 4);
            size_t src = (size_t)(m0 + row) * K + k0 + ch * 8;
            cp16(d, Ah + src);
            cp16(d + HPLW * 4, Al + src);
        }
#pragma unroll
        for (int i = 0; i < 2; i++) {
            int cid = tid * 2 + i;
            int row = cid >> 2, ch = cid & 3;
            uint32_t d = sb + (uint32_t)((2 * HPLW + row * HROW + ch * 4) * 4);
            size_t src = (size_t)(n0 + row) * K + k0 + ch * 8;
            cp16(d, Bh + src);
            cp16(d + HPLW * 4, Bl + src);
        }
        asm volatile("cp.async.commit_group;");
    };

    float acc[4][4][4];
#pragma unroll
    for (int i = 0; i < 4; i++)
#pragma unroll
        for (int j = 0; j < 4; j++)
#pragma unroll
            for (int l = 0; l < 4; l++) acc[i][j][l] = 0.f;

    load_stage(0, 0);
    if (KT > 1) load_stage(1, 1);
    asm volatile("cp.async.wait_group 1;");
    __syncthreads();

    for (int kt = 0; kt < KT; kt++) {
        const int cur = kt & 1;
        const uint32_t uA = sbase + (uint32_t)(cur * HSTW * 4);
        const uint32_t uB = uA + (uint32_t)(2 * HPLW * 4);

#pragma unroll
        for (int wc = 0; wc < 16; wc += 8) {
            uint32_t aH[4][4], aL[4][4], bH[4][2], bL[4][2];
#pragma unroll
            for (int mt = 0; mt < 4; mt++) {
                uint32_t ad = uA + (uint32_t)((aRowOff + mt * 16 * HROW + wc) * 4);
                LDSM_X4(aH[mt][0], aH[mt][1], aH[mt][2], aH[mt][3], ad);
                LDSM_X4(aL[mt][0], aL[mt][1], aL[mt][2], aL[mt][3], ad + HPLW * 4);
            }
#pragma unroll
            for (int pr = 0; pr < 2; pr++) {
                uint32_t bd = uB + (uint32_t)((bRowOff + pr * 16 * HROW + wc) * 4);
                LDSM_X4(bH[2 * pr][0], bH[2 * pr][1], bH[2 * pr + 1][0], bH[2 * pr + 1][1], bd);
                LDSM_X4(bL[2 * pr][0], bL[2 * pr][1], bL[2 * pr + 1][0], bL[2 * pr + 1][1],
                        bd + HPLW * 4);
            }
#pragma unroll
            for (int mt = 0; mt < 4; mt++)
#pragma unroll
                for (int nt = 0; nt < 4; nt++) {
                    mma_f16(acc[mt][nt], aH[mt], bH[nt]);
                    mma_f16(acc[mt][nt], aH[mt], bL[nt]);
                    mma_f16(acc[mt][nt], aL[mt], bH[nt]);
                }
        }
        __syncthreads();
        if (kt + 2 < KT) {
            load_stage(kt + 2, cur);
            asm volatile("cp.async.wait_group 1;");
        } else if (kt + 1 < KT) {
            asm volatile("cp.async.wait_group 0;");
        }
        __syncthreads();
    }

    if (a.mode == 0) {
        if (a.packN > 0) {
#pragma unroll
            for (int mt = 0; mt < 4; mt++) {
#pragma unroll
                for (int nt = 0; nt < 4; nt++) {
#pragma unroll
                    for (int v = 0; v < 4; v++) {
                        int gm = m0 + wm * 64 + mt * 16 + lr + (v >> 1) * 8;
                        int gn = n0 + wn * 32 + nt * 8 + lc * 2 + (v & 1);
                        if (gn < a.packN)
                            a.C[(size_t)gm * a.ldc + gn] = acc[mt][nt][v] + a.bias[gn];
                    }
                }
            }
        } else {
#pragma unroll
            for (int mt = 0; mt < 4; mt++) {
                int gm0 = m0 + wm * 64 + mt * 16 + lr;
                int gm1 = gm0 + 8;
#pragma unroll
                for (int nt = 0; nt < 4; nt++) {
                    int gn = n0 + wn * 32 + nt * 8 + lc * 2;
                    float b0 = 0.f, b1 = 0.f;
                    if (a.bias) { b0 = a.bias[gn]; b1 = a.bias[gn + 1]; }
                    float2 v0 = make_float2(acc[mt][nt][0] + b0, acc[mt][nt][1] + b1);
                    float2 v1 = make_float2(acc[mt][nt][2] + b0, acc[mt][nt][3] + b1);
                    if (a.addm) {
                        float2 m0v = *(const float2*)(a.addm + (size_t)gm0 * a.ldc + gn);
                        float2 m1v = *(const float2*)(a.addm + (size_t)gm1 * a.ldc + gn);
                        v0.x += m0v.x; v0.y += m0v.y;
                        v1.x += m1v.x; v1.y += m1v.y;
                    }
                    *(float2*)(a.C + (size_t)gm0 * a.ldc + gn) = v0;
                    *(float2*)(a.C + (size_t)gm1 * a.ldc + gn) = v1;
                    if (a.Ch) {
                        __half hx, lx, hy, ly;
                        split_h(v0.x, hx, lx); split_h(v0.y, hy, ly);
                        *(__half2*)(a.Ch + (size_t)gm0 * a.ldc + gn) = __halves2half2(hx, hy);
                        *(__half2*)(a.Cl + (size_t)gm0 * a.ldc + gn) = __halves2half2(lx, ly);
                        split_h(v1.x, hx, lx); split_h(v1.y, hy, ly);
                        *(__half2*)(a.Ch + (size_t)gm1 * a.ldc + gn) = __halves2half2(hx, hy);
                        *(__half2*)(a.Cl + (size_t)gm1 * a.ldc + gn) = __halves2half2(lx, ly);
                    }
                }
            }
        }
    } else {
        // GRU-fin: n = tanh(acc + XW3 + b); h = (1-z)h + z n
#pragma unroll
        for (int mt = 0; mt < 4; mt++) {
#pragma unroll
            for (int nt = 0; nt < 4; nt++) {
#pragma unroll
                for (int v = 0; v < 4; v++) {
                    int gm = m0 + wm * 64 + mt * 16 + lr + (v >> 1) * 8;
                    int gn = n0 + wn * 32 + nt * 8 + lc * 2 + (v & 1);
                    size_t off = (size_t)gm * a.ldc + gn;
                    float n = tanhf(acc[mt][nt][v] + a.XW3[(size_t)gm * a.ldxw + gn]
                                    + a.bias[gn]);
                    float z = a.Z[off];
                    float h = (1.f - z) * a.Hh[off] + z * n;
                    a.Hh[off] = h;
                    __half ph, pl;
                    split_h(h, ph, pl);
                    a.Ch[off] = ph;
                    a.Cl[off] = pl;
                }
            }
        }
    }
}

__global__ __launch_bounds__(256, 2) void hgemm_kernel(HGArgs a) {
    hgemm_body(a, blockIdx.x);
}
__global__ __launch_bounds__(256, 2) void hgemm_dual_kernel(HGArgs a, HGArgs b, int na) {
    int bx = blockIdx.x;
    if (bx < na) hgemm_body(a, bx);
    else hgemm_body(b, bx - na);
}
__global__ __launch_bounds__(256, 2) void hgemm_tri_kernel(HGArgs a, HGArgs b, HGArgs c,
                                                           int na, int nab) {
    int bx = blockIdx.x;
    if (bx < na) hgemm_body(a, bx);
    else if (bx < nab) hgemm_body(b, bx - na);
    else hgemm_body(c, bx - nab);
}

// ---------------- split kernels ---------------------------------------------
__global__ void asplit_kernel(const float2* __restrict__ in,
                              __half2* __restrict__ hi, __half2* __restrict__ lo, int n2) {
    int i = blockIdx.x * blockDim.x + threadIdx.x;
    if (i >= n2) return;
    float2 v = in[i];
    __half hx, lx, hy, ly;
    split_h(v.x, hx, lx);
    split_h(v.y, hy, ly);
    hi[i] = __halves2half2(hx, hy);
    lo[i] = __halves2half2(lx, ly);
}

__global__ void wsplit_kernel(const float* __restrict__ W, int ldw, int c0, int wcols, int wrows,
                              __half* __restrict__ Th, __half* __restrict__ Tl, int K) {
    __shared__ float t[32][33];
    int kb = blockIdx.y * 32, nb = blockIdx.x * 32;
    int tx = threadIdx.x, ty = threadIdx.y;
    int col = c0 + nb + tx;
#pragma unroll
    for (int i = 0; i < 32; i += 8) {
        int kr = kb + ty + i;
        t[ty + i][tx] = (col < wcols && kr < wrows) ? W[(size_t)kr * ldw + col] : 0.f;
    }
    __syncthreads();
#pragma unroll
    for (int i = 0; i < 32; i += 8) {
        int n = nb + ty + i, k = kb + tx;
        __half h, l;
        split_h(t[tx][ty + i], h, l);
        Th[(size_t)n * K + k] = h;
        Tl[(size_t)n * K + k] = l;
    }
}

__global__ void biaspad_kernel(const float* __restrict__ b, float* __restrict__ out,
                               int n, int npad) {
    int i = blockIdx.x * blockDim.x + threadIdx.x;
    if (i < npad) out[i] = (i < n) ? b[i] : 0.f;
}

// ---------------- generic fp32 SGEMM (WCOMB only) -----------------------------
__global__ __launch_bounds__(256) void sgemm_kernel(
    const float* __restrict__ A, int lda,
    const float* __restrict__ B, int ldb,
    float* __restrict__ C, int ldc,
    int M, int N, int K)
{
    __shared__ float As[8][132];
    __shared__ float Bs[8][128];
    const int tid = threadIdx.x;
    const int tx = tid & 15;
    const int ty = tid >> 4;
    const int m0 = blockIdx.y * 128;
    const int n0 = blockIdx.x * 128;

    float acc[8][8];
#pragma unroll
    for (int i = 0; i < 8; i++)
#pragma unroll
        for (int j = 0; j < 8; j++) acc[i][j] = 0.f;

    for (int k0 = 0; k0 < K; k0 += 8) {
#pragma unroll
        for (int l = 0; l < 4; l++) {
            int e = tid + l * 256;
            int r = e >> 3, c = e & 7;
            float v = 0.f;
            int gm = m0 + r, gk = k0 + c;
            if (gm < M && gk < K) v = A[(size_t)gm * lda + gk];
            As[c][r] = v;
        }
#pragma unroll
        for (int l = 0; l < 4; l++) {
            int e = tid + l * 256;
            int r = e >> 7, c = e & 127;
            float v = 0.f;
            int gk = k0 + r, gn = n0 + c;
            if (gk < K && gn < N) v = B[(size_t)gk * ldb + gn];
            Bs[r][c] = v;
        }
        __syncthreads();
#pragma unroll
        for (int k = 0; k < 8; k++) {
            float a[8], b[8];
#pragma unroll
            for (int i = 0; i < 8; i++) a[i] = As[k][ty * 8 + i];
#pragma unroll
            for (int j = 0; j < 8; j++) b[j] = Bs[k][tx * 8 + j];
#pragma unroll
            for (int i = 0; i < 8; i++)
#pragma unroll
                for (int j = 0; j < 8; j++)
                    acc[i][j] = fmaf(a[i], b[j], acc[i][j]);
        }
        __syncthreads();
    }
#pragma unroll
    for (int i = 0; i < 8; i++) {
        int gm = m0 + ty * 8 + i;
        if (gm >= M) continue;
#pragma unroll
        for (int j = 0; j < 8; j++) {
            int gn = n0 + tx * 8 + j;
            if (gn >= N) continue;
            C[(size_t)gm * ldc + gn] = acc[i][j];
        }
    }
}

// ---------------- decode rel_inds --------------------------------------------
__global__ __launch_bounds__(1024) void decode_rel_kernel(const void* rel_raw) {
    __shared__ int s_or;
    int tid = threadIdx.x;
    if (tid == 0) s_or = 0;
    __syncthreads();
    const int* v32 = (const int*)rel_raw;
    int acc = 0;
    for (int i = tid; i < (3 * RR) / 2; i += 1024) acc |= v32[2 * i + 1];
    if (acc) atomicOr(&s_or, 1);
    __syncthreads();
    bool is64 = (s_or == 0);
    if (is64) {
        const long long* v = (const long long*)rel_raw;
        for (int r = tid; r < RR; r += 1024) {
            g_s_idx[r] = (int)v[3 * r + 1];
            g_o_idx[r] = (int)v[3 * r + 2];
        }
    } else {
        for (int r = tid; r < RR; r += 1024) {
            g_s_idx[r] = v32[3 * r + 1];
            g_o_idx[r] = v32[3 * r + 2];
        }
    }
}

// ---------------- softmax -> padded fp16 planes -------------------------------
__global__ void softmax_split_kernel(const float* __restrict__ X,
                                     __half* __restrict__ Ph, __half* __restrict__ Pl) {
    int row = blockIdx.x;
    int tid = threadIdx.x;
    __shared__ float red[256];
    const float* x = X + (size_t)row * NOC_;
    float m = -3.4e38f;
    for (int c = tid; c < NOC_; c += 256) m = fmaxf(m, x[c]);
    red[tid] = m; __syncthreads();
    for (int s = 128; s > 0; s >>= 1) {
        if (tid < s) red[tid] = fmaxf(red[tid], red[tid + s]);
        __syncthreads();
    }
    m = red[0]; __syncthreads();
    float sum = 0.f;
    for (int c = tid; c < NOC_; c += 256) sum += expf(x[c] - m);
    red[tid] = sum; __syncthreads();
    for (int s = 128; s > 0; s >>= 1) {
        if (tid < s) red[tid] += red[tid + s];
        __syncthreads();
    }
    float inv = 1.f / red[0];
    for (int c = tid; c < KEMB; c += 256) {
        float v = (c < NOC_) ? expf(x[c] - m) * inv : 0.f;
        __half h, l;
        split_h(v, h, l);
        Ph[(size_t)row * KEMB + c] = h;
        Pl[(size_t)row * KEMB + c] = l;
    }
}

__global__ void softmax_kernel(const float* __restrict__ X, float* __restrict__ Y) {
    int row = blockIdx.x;
    int tid = threadIdx.x;
    __shared__ float red[256];
    const float* x = X + (size_t)row * NOC_;
    float m = -3.4e38f;
    for (int c = tid; c < NOC_; c += 256) m = fmaxf(m, x[c]);
    red[tid] = m; __syncthreads();
    for (int s = 128; s > 0; s >>= 1) {
        if (tid < s) red[tid] = fmaxf(red[tid], red[tid + s]);
        __syncthreads();
    }
    m = red[0]; __syncthreads();
    float sum = 0.f;
    for (int c = tid; c < NOC_; c += 256) sum += expf(x[c] - m);
    red[tid] = sum; __syncthreads();
    for (int s = 128; s > 0; s >>= 1) {
        if (tid < s) red[tid] += red[tid + s];
        __syncthreads();
    }
    float inv = 1.f / red[0];
    for (int c = tid; c < NOC_; c += 256)
        Y[(size_t)row * NOC_ + c] = expf(x[c] - m) * inv;
}

// ---------------- XWR[r] = HW[s_r] + HW[o_r]  (float4) ------------------------
__global__ void xwr_gather_kernel(const float4* __restrict__ HW, float4* __restrict__ XWR) {
    int i = blockIdx.x * blockDim.x + threadIdx.x;
    if (i >= RR * 384) return;
    int r = i / 384;
    int c = i - r * 384;
    float4 a = HW[g_s_idx[r] * 384 + c];
    float4 b = HW[g_o_idx[r] * 384 + c];
    XWR[i] = make_float4(a.x + b.x, a.y + b.y, a.z + b.z, a.w + b.w);
}

// ---------------- m_obj scatter -> planes -------------------------------------
__global__ __launch_bounds__(512) void scatter_obj_kernel(const float* __restrict__ HM, int ldhm,
                                                          __half* __restrict__ Mh,
                                                          __half* __restrict__ Ml) {
    int obj = blockIdx.x;
    int c = threadIdx.x;
    int img = obj >> 6;
    int base = img * RPI_;
    __shared__ int ss[RPI_];
    __shared__ int oo[RPI_];
    for (int j = c; j < RPI_; j += 512) {
        ss[j] = g_s_idx[base + j];
        oo[j] = g_o_idx[base + j];
    }
    __syncthreads();
    float acc = 0.f;
    for (int j = 0; j < RPI_; j++) {
        if (ss[j] == obj) acc += HM[(size_t)(base + j) * ldhm + c];
        if (oo[j] == obj) acc += HM[(size_t)(base + j) * ldhm + c];
    }
    __half h, l;
    split_h(acc, h, l);
    Mh[(size_t)obj * HD + c] = h;
    Ml[(size_t)obj * HD + c] = l;
}

// ---------------- GRU z, r*h -> planes ----------------------------------------
__global__ void gru_zr_kernel(const float* __restrict__ XW, int ldxw,
                              const float* __restrict__ HU, int ldhu,
                              const float* __restrict__ b, const float* __restrict__ Hh,
                              float* __restrict__ Z,
                              __half* __restrict__ RHh, __half* __restrict__ RHl, int M) {
    int idx = blockIdx.x * blockDim.x + threadIdx.x;
    if (idx >= M * HD) return;
    int row = idx >> 9;
    int c = idx & 511;
    float z = XW[(size_t)row * ldxw + c] + HU[(size_t)row * ldhu + c] + b[c];
    float r = XW[(size_t)row * ldxw + 512 + c] + HU[(size_t)row * ldhu + 512 + c] + b[512 + c];
    z = 1.f / (1.f + expf(-z));
    r = 1.f / (1.f + expf(-r));
    Z[idx] = z;
    __half h, l;
    split_h(r * Hh[idx], h, l);
    RHh[idx] = h; RHl[idx] = l;
}

// ---------------- NMS ----------------------------------------------------------
__global__ __launch_bounds__(512) void nms_kernel(const float* __restrict__ SP,
                                                  const float* __restrict__ BOX,
                                                  unsigned char* __restrict__ KEEP) {
    int cls = blockIdx.x + 1;
    int tid = threadIdx.x;
    __shared__ float sc[NN];
    __shared__ int sidx[NN];
    __shared__ float bx[NN][4];
    __shared__ float area[NN];
    __shared__ unsigned char keep[NN];

    sc[tid] = SP[(size_t)tid * NOC_ + cls];
    sidx[tid] = tid;
    __syncthreads();

    for (int k = 2; k <= NN; k <<= 1) {
        for (int j = k >> 1; j > 0; j >>= 1) {
            int ixj = tid ^ j;
            if (ixj > tid) {
                float s1 = sc[tid], s2 = sc[ixj];
                int i1 = sidx[tid], i2 = sidx[ixj];
                bool dir = ((tid & k) == 0);
                bool precBA = (s2 > s1) || (s2 == s1 && i2 < i1);
                if (precBA == dir) {
                    sc[tid] = s2; sc[ixj] = s1;
                    sidx[tid] = i2; sidx[ixj] = i1;
                }
            }
            __syncthreads();
        }
    }

    int oi = sidx[tid];
    float x1 = BOX[((size_t)oi * NOC_ + cls) * 4 + 0];
    float y1 = BOX[((size_t)oi * NOC_ + cls) * 4 + 1];
    float x2 = BOX[((size_t)oi * NOC_ + cls) * 4 + 2];
    float y2 = BOX[((size_t)oi * NOC_ + cls) * 4 + 3];
    bx[tid][0] = x1; bx[tid][1] = y1; bx[tid][2] = x2; bx[tid][3] = y2;
    area[tid] = (x2 - x1) * (y2 - y1);
    keep[tid] = 1;
    __syncthreads();

    for (int i = 0; i < NN - 1; i++) {
        if (tid > i && keep[i] && keep[tid]) {
            float lx = fmaxf(bx[i][0], x1);
            float ly = fmaxf(bx[i][1], y1);
            float rx = fminf(bx[i][2], x2);
            float ry = fminf(bx[i][3], y2);
            float w = fmaxf(rx - lx, 0.f);
            float h = fmaxf(ry - ly, 0.f);
            float inter = w * h;
            float iou = inter / (area[i] + area[tid] - inter + 1e-9f);
            if (iou > IOU_THR_) keep[tid] = 0;
        }
        __syncthreads();
    }
    KEEP[(size_t)(cls - 1) * NN + oi] = keep[tid];
}

// ---------------- obj_preds -----------------------------------------------------
__global__ void preds_kernel(const float* __restrict__ SP, const unsigned char* __restrict__ KEEP,
                             float* __restrict__ out) {
    int n = blockIdx.x * blockDim.x + threadIdx.x;
    if (n >= NN) return;
    float best = -1.f;
    int bi = 0;
    for (int c = 0; c < 150; c++) {
        float v = KEEP[(size_t)c * NN + n] ? SP[(size_t)n * NOC_ + c + 1] : 0.f;
        if (v > best) { best = v; bi = c; }
    }
    out[n] = (float)(bi + 1);
}

// ---------------- host orchestration --------------------------------------------
struct Scratch {
    float *FO, *HOBJ, *HREL, *XWR, *HMHU, *HW, *ZR;
    float *XWO, *HUO, *ZO, *SP, *WCOMB, *BCR, *BCO;
    unsigned char* KEEP;
    __half *Pa_h, *Pa_l, *Pb_h, *Pb_l, *Ps_h, *Ps_l, *Ph_h, *Ph_l;
    __half *Po1_h, *Po1_l, *Po2_h, *Po2_l, *Po3_h, *Po3_l, *OP_h, *OP_l;
    __half *Wop_h, *Wop_l, *Wrp_h, *Wrp_l, *Wemb_h, *Wemb_l;
    __half *Wcb_h, *Wcb_l, *Wct_h, *Wct_l;
    __half *Ugr2_h, *Ugr2_l, *Wgo_h, *Wgo_l, *Ugo_h, *Ugo_l;
    __half *Wcr_h, *Wcr_l, *Wco_h, *Wco_l;
    bool init = false;
};
static Scratch g_sc;

static void init_scratch() {
    if (g_sc.init) return;
    void* p;
#define GET(sym, fld, T) cudaGetSymbolAddress(&p, sym); g_sc.fld = (T*)p;
    GET(g_fo, FO, float)
    GET(g_h_obj, HOBJ, float)
    GET(g_h_rel, HREL, float)
    GET(g_xw_rel, XWR, float)
    GET(g_hmhu, HMHU, float)
    GET(g_hw, HW, float)
    GET(g_z_rel, ZR, float)
    GET(g_xw_obj, XWO, float)
    GET(g_hu_obj, HUO, float)
    GET(g_z_obj, ZO, float)
    GET(g_sp, SP, float)
    GET(g_wcomb, WCOMB, float)
    GET(g_bcr, BCR, float)
    GET(g_bco, BCO, float)
    GET(g_keep, KEEP, unsigned char)
    GET(g_Pa_h, Pa_h, __half) GET(g_Pa_l, Pa_l, __half)
    GET(g_Pb_h, Pb_h, __half) GET(g_Pb_l, Pb_l, __half)
    GET(g_Ps_h, Ps_h, __half) GET(g_Ps_l, Ps_l, __half)
    GET(g_Ph_h, Ph_h, __half) GET(g_Ph_l, Ph_l, __half)
    GET(g_Po1_h, Po1_h, __half) GET(g_Po1_l, Po1_l, __half)
    GET(g_Po2_h, Po2_h, __half) GET(g_Po2_l, Po2_l, __half)
    GET(g_Po3_h, Po3_h, __half) GET(g_Po3_l, Po3_l, __half)
    GET(g_OP_h, OP_h, __half)  GET(g_OP_l, OP_l, __half)
    GET(g_Wop_h, Wop_h, __half) GET(g_Wop_l, Wop_l, __half)
    GET(g_Wrp_h, Wrp_h, __half) GET(g_Wrp_l, Wrp_l, __half)
    GET(g_Wemb_h, Wemb_h, __half) GET(g_Wemb_l, Wemb_l, __half)
    GET(g_Wcb_h, Wcb_h, __half) GET(g_Wcb_l, Wcb_l, __half)
    GET(g_Wct_h, Wct_h, __half) GET(g_Wct_l, Wct_l, __half)
    GET(g_Ugr2_h, Ugr2_h, __half) GET(g_Ugr2_l, Ugr2_l, __half)
    GET(g_Wgo_h, Wgo_h, __half) GET(g_Wgo_l, Wgo_l, __half)
    GET(g_Ugo_h, Ugo_h, __half) GET(g_Ugo_l, Ugo_l, __half)
    GET(g_Wcr_h, Wcr_h, __half) GET(g_Wcr_l, Wcr_l, __half)
    GET(g_Wco_h, Wco_h, __half) GET(g_Wco_l, Wco_l, __half)
#undef GET
    cudaFuncSetAttribute(hgemm_kernel, cudaFuncAttributeMaxDynamicSharedMemorySize, HG_SMEM);
    cudaFuncSetAttribute(hgemm_dual_kernel, cudaFuncAttributeMaxDynamicSharedMemorySize, HG_SMEM);
    cudaFuncSetAttribute(hgemm_tri_kernel, cudaFuncAttributeMaxDynamicSharedMemorySize, HG_SMEM);
    g_sc.init = true;
}

static HGArgs mkargs(const __half* Ah, const __half* Al, const __half* Bh, const __half* Bl,
                     float* C, int ldc, int M, int N, int K, const float* bias,
                     __half* Ch = nullptr, __half* Cl = nullptr) {
    HGArgs a;
    a.Ah = Ah; a.Al = Al; a.Bh = Bh; a.Bl = Bl;
    a.C = C; a.ldc = ldc; a.M = M; a.N = N; a.K = K;
    a.bias = bias; a.addm = nullptr; a.Ch = Ch; a.Cl = Cl;
    a.mode = 0; a.packN = 0;
    a.XW3 = nullptr; a.ldxw = 0; a.Z = nullptr; a.Hh = nullptr;
    return a;
}

static int nblk(const HGArgs& a) { return (a.M / 128) * (a.N / 128); }
static void hgemm1(const HGArgs& a) {
    hgemm_kernel<<<nblk(a), 256, HG_SMEM>>>(a);
}
static void hgemm2(const HGArgs& a, const HGArgs& b) {
    hgemm_dual_kernel<<<nblk(a) + nblk(b), 256, HG_SMEM>>>(a, b, nblk(a));
}
static void hgemm3(const HGArgs& a, const HGArgs& b, const HGArgs& c) {
    int na = nblk(a), nab = na + nblk(b);
    hgemm_tri_kernel<<<nab + nblk(c), 256, HG_SMEM>>>(a, b, c, na, nab);
}

static void asplit(const float* A, __half* hi, __half* lo, int n) {
    int n2 = n / 2;
    asplit_kernel<<<(n2 + 255) / 256, 256>>>((const float2*)A, (__half2*)hi, (__half2*)lo, n2);
}

static void wsplit(const float* W, int ldw, int c0, int wcols, int wrows,
                   __half* Th, __half* Tl, int K, int ncols) {
    dim3 g(ncols / 32, K / 32);
    wsplit_kernel<<<g, dim3(32, 8)>>>(W, ldw, c0, wcols, wrows, Th, Tl, K);
}

extern "C" void kernel_launch(void* const* d_in, const int* in_sizes, int n_in,
                              void* d_out, int out_size) {
    (void)in_sizes; (void)n_in; (void)out_size;
    init_scratch();

    const float* obj_fmaps  = (const float*)d_in[1];
    const float* obj_logits = (const float*)d_in[2];
    const void*  rel_raw    = d_in[3];
    const float* vr         = (const float*)d_in[4];
    const float* boxes      = (const float*)d_in[5];
    const float* W_obj_proj = (const float*)d_in[6];
    const float* b_obj_proj = (const float*)d_in[7];
    const float* W_rel_proj = (const float*)d_in[8];
    const float* b_rel_proj = (const float*)d_in[9];
    const float* W_emb      = (const float*)d_in[10];
    const float* W_msg_rel  = (const float*)d_in[11];
    const float* W_msg_obj  = (const float*)d_in[12];
    const float* W_gru_obj  = (const float*)d_in[13];
    const float* U_gru_obj  = (const float*)d_in[14];
    const float* b_gru_obj  = (const float*)d_in[15];
    const float* W_gru_rel  = (const float*)d_in[16];
    const float* U_gru_rel  = (const float*)d_in[17];
    const float* b_gru_rel  = (const float*)d_in[18];
    const float* W_cls_rel  = (const float*)d_in[19];
    const float* b_cls_rel  = (const float*)d_in[20];
    const float* W_cls_obj  = (const float*)d_in[21];
    const float* b_cls_obj  = (const float*)d_in[22];

    float* out_obj_logits = (float*)d_out;
    float* out_preds      = out_obj_logits + NN * NOC_;
    float* out_rel_logits = out_preds + NN;

    // 0. decode; weight planes
    decode_rel_kernel<<<1, 1024>>>(rel_raw);
    wsplit(W_obj_proj, HD, 0, HD, OBJD, g_sc.Wop_h, g_sc.Wop_l, OBJD, HD);
    wsplit(W_rel_proj, HD, 0, HD, OBJD, g_sc.Wrp_h, g_sc.Wrp_l, OBJD, HD);
    wsplit(W_emb, HD, 0, HD, NOC_, g_sc.Wemb_h, g_sc.Wemb_l, KEMB, HD);
    wsplit(W_msg_obj, HD, 0, HD, HD, g_sc.Wct_h, g_sc.Wct_l, HD, HD);
    wsplit(U_gru_rel, 3 * HD, 0, 3 * HD, HD, g_sc.Wct_h + (size_t)HD * HD,
           g_sc.Wct_l + (size_t)HD * HD, HD, 2 * HD);
    wsplit(U_gru_rel, 3 * HD, 2 * HD, 3 * HD, HD, g_sc.Ugr2_h, g_sc.Ugr2_l, HD, HD);
    wsplit(W_gru_obj, 3 * HD, 0, 3 * HD, HD, g_sc.Wgo_h, g_sc.Wgo_l, HD, 3 * HD);
    wsplit(U_gru_obj, 3 * HD, 0, 3 * HD, HD, g_sc.Ugo_h, g_sc.Ugo_l, HD, 3 * HD);
    wsplit(W_cls_rel, NRC_, 0, NRC_, HD, g_sc.Wcr_h, g_sc.Wcr_l, HD, 128);
    wsplit(W_cls_obj, NOC_, 0, NOC_, HD, g_sc.Wco_h, g_sc.Wco_l, HD, 256);
    biaspad_kernel<<<1, 128>>>(b_cls_rel, g_sc.BCR, NRC_, 128);
    biaspad_kernel<<<1, 256>>>(b_cls_obj, g_sc.BCO, NOC_, 256);
    {
        dim3 g((3 * HD + 127) / 128, (HD + 127) / 128);
        sgemm_kernel<<<g, 256>>>(W_msg_rel, HD, W_gru_rel, 3 * HD, g_sc.WCOMB, 3 * HD,
                                 HD, 3 * HD, HD);
    }
    wsplit(g_sc.WCOMB, 3 * HD, 0, 3 * HD, HD, g_sc.Wcb_h, g_sc.Wcb_l, HD, 3 * HD);

    // 1. activation splits
    asplit(obj_fmaps, g_sc.Pb_h, g_sc.Pb_l, NN * OBJD);
    asplit(vr, g_sc.Pa_h, g_sc.Pa_l, RR * OBJD);
    softmax_split_kernel<<<NN, 256>>>(obj_logits, g_sc.OP_h, g_sc.OP_l);

    // 2. fo + h_rel (paired)
    hgemm2(mkargs(g_sc.Pb_h, g_sc.Pb_l, g_sc.Wop_h, g_sc.Wop_l, g_sc.FO, HD,
                  NN, HD, OBJD, b_obj_proj),
           mkargs(g_sc.Pa_h, g_sc.Pa_l, g_sc.Wrp_h, g_sc.Wrp_l, g_sc.HREL, HD,
                  RR, HD, OBJD, b_rel_proj, g_sc.Ph_h, g_sc.Ph_l));

    // 3. h_obj = obj_probs @ W_emb + fo
    {
        HGArgs a = mkargs(g_sc.OP_h, g_sc.OP_l, g_sc.Wemb_h, g_sc.Wemb_l, g_sc.HOBJ, HD,
                          NN, HD, KEMB, nullptr, g_sc.Po2_h, g_sc.Po2_l);
        a.addm = g_sc.FO;
        hgemm1(a);
    }

    const int EW_REL = (RR * HD + 255) / 256;
    const int EW_OBJ = (NN * HD + 255) / 256;
    const int XG_BLOCKS = (RR * 384 + 255) / 256;
    const __half* Ugo2_h = g_sc.Ugo_h + (size_t)2 * HD * HD;
    const __half* Ugo2_l = g_sc.Ugo_l + (size_t)2 * HD * HD;

    for (int t = 0; t < TSTEPS; t++) {
        // HW = HOBJ@WCOMB ; HMHU = h_rel@WCAT ; HUO = HOBJ@Ugo01  (one tri launch)
        hgemm3(mkargs(g_sc.Po2_h, g_sc.Po2_l, g_sc.Wcb_h, g_sc.Wcb_l, g_sc.HW, 3 * HD,
                      NN, 3 * HD, HD, nullptr),
               mkargs(g_sc.Ph_h, g_sc.Ph_l, g_sc.Wct_h, g_sc.Wct_l, g_sc.HMHU, 3 * HD,
                      RR, 3 * HD, HD, nullptr),
               mkargs(g_sc.Po2_h, g_sc.Po2_l, g_sc.Ugo_h, g_sc.Ugo_l, g_sc.HUO, 2 * HD,
                      NN, 2 * HD, HD, nullptr));
        // XWR[r] = HW[s_r] + HW[o_r]
        xwr_gather_kernel<<<XG_BLOCKS, 256>>>((const float4*)g_sc.HW, (float4*)g_sc.XWR);
        scatter_obj_kernel<<<NN, 512>>>(g_sc.HMHU, 3 * HD, g_sc.Po1_h, g_sc.Po1_l);

        // GRU rel zr; then (rel NU+fin) paired with XWO
        gru_zr_kernel<<<EW_REL, 256>>>(g_sc.XWR, 3 * HD, g_sc.HMHU + HD, 3 * HD,
                                       b_gru_rel, g_sc.HREL, g_sc.ZR, g_sc.Ps_h, g_sc.Ps_l, RR);
        {
            HGArgs fin = mkargs(g_sc.Ps_h, g_sc.Ps_l, g_sc.Ugr2_h, g_sc.Ugr2_l,
                                nullptr, HD, RR, HD, HD, b_gru_rel + 2 * HD,
                                g_sc.Ph_h, g_sc.Ph_l);
            fin.mode = 1; fin.XW3 = g_sc.XWR + 2 * HD; fin.ldxw = 3 * HD;
            fin.Z = g_sc.ZR; fin.Hh = g_sc.HREL;
            hgemm2(fin,
                   mkargs(g_sc.Po1_h, g_sc.Po1_l, g_sc.Wgo_h, g_sc.Wgo_l, g_sc.XWO, 3 * HD,
                          NN, 3 * HD, HD, nullptr));
        }

        // GRU obj zr; NU+fin
        gru_zr_kernel<<<EW_OBJ, 256>>>(g_sc.XWO, 3 * HD, g_sc.HUO, 2 * HD,
                                       b_gru_obj, g_sc.HOBJ, g_sc.ZO, g_sc.Po3_h, g_sc.Po3_l, NN);
        {
            HGArgs fin = mkargs(g_sc.Po3_h, g_sc.Po3_l, Ugo2_h, Ugo2_l,
                                nullptr, HD, NN, HD, HD, b_gru_obj + 2 * HD,
                                g_sc.Po2_h, g_sc.Po2_l);
            fin.mode = 1; fin.XW3 = g_sc.XWO + 2 * HD; fin.ldxw = 3 * HD;
            fin.Z = g_sc.ZO; fin.Hh = g_sc.HOBJ;
            hgemm1(fin);
        }
    }

    // classifiers write straight into d_out (packN scalar stores)
    {
        HGArgs rc = mkargs(g_sc.Ph_h, g_sc.Ph_l, g_sc.Wcr_h, g_sc.Wcr_l,
                           out_rel_logits, NRC_, RR, 128, HD, g_sc.BCR);
        rc.packN = NRC_;
        HGArgs oc = mkargs(g_sc.Po2_h, g_sc.Po2_l, g_sc.Wco_h, g_sc.Wco_l,
                           out_obj_logits, NOC_, NN, 256, HD, g_sc.BCO);
        oc.packN = NOC_;
        hgemm2(rc, oc);
    }

    // softmax -> NMS -> preds
    softmax_kernel<<<NN, 256>>>(out_obj_logits, g_sc.SP);
    nms_kernel<<<150, 512>>>(g_sc.SP, boxes, g_sc.KEEP);
    preds_kernel<<<(NN + 255) / 256, 256>>>(g_sc.SP, g_sc.KEEP, out_preds);
}

// round 14
// speedup vs baseline: 1.1738x; 1.1023x over previous
#include <cuda_runtime.h>
#include <cuda_bf16.h>
#include <cuda_fp16.h>
#include <math.h>
#include <stdint.h>

// ---------------- problem constants ----------------
#define BIMG 8
#define OPI_ 64
#define RPI_ 1024
#define NN 512
#define RR 8192
#define OBJD 4096
#define HD 512
#define NOC_ 151
#define NRC_ 51
#define TSTEPS 3
#define IOU_THR_ 0.3f
#define KEMB 160

// ---------------- helpers ----------------------------------------------------
__device__ __forceinline__ void split_h(float v, __half& hi, __half& lo) {
    hi = __float2half_rn(v);
    lo = __float2half_rn(v - __half2float(hi));
}
__device__ __forceinline__ void mma_f16(float* c, const uint32_t* a, const uint32_t* b) {
    asm volatile(
        "mma.sync.aligned.m16n8k16.row.col.f32.f16.f16.f32 "
        "{%0,%1,%2,%3},{%4,%5,%6,%7},{%8,%9},{%0,%1,%2,%3};"
        : "+f"(c[0]), "+f"(c[1]), "+f"(c[2]), "+f"(c[3])
        : "r"(a[0]), "r"(a[1]), "r"(a[2]), "r"(a[3]), "r"(b[0]), "r"(b[1]));
}
__device__ __forceinline__ void cp16(uint32_t dst, const void* src) {
    asm volatile("cp.async.cg.shared.global [%0], [%1], 16;" :: "r"(dst), "l"(src));
}
#define LDSM_X4(r0, r1, r2, r3, addr) \
    asm volatile("ldmatrix.sync.aligned.m8n8.x4.shared.b16 {%0,%1,%2,%3}, [%4];" \
        : "=r"(r0), "=r"(r1), "=r"(r2), "=r"(r3) : "r"(addr))

// ---------------- f32 scratch ------------------------------------------------
__device__ float g_fo[NN * HD];
__device__ float g_h_obj[NN * HD];
__device__ float g_h_rel[RR * HD];
__device__ float g_xw_rel[RR * 3 * HD];
__device__ float g_hmhu[RR * 3 * HD];
__device__ float g_hw[NN * 3 * HD];
__device__ float g_z_rel[RR * HD];
__device__ float g_xw_obj[NN * 3 * HD];
__device__ float g_hu_obj[NN * 2 * HD];
__device__ float g_z_obj[NN * HD];
__device__ float g_sp[NN * NOC_];
__device__ float g_wcomb[HD * 3 * HD];
__device__ float g_bcr[128];
__device__ float g_bco[256];
__device__ unsigned char g_keep[150 * NN];
__device__ int g_s_idx[RR];
__device__ int g_o_idx[RR];
__device__ int g_adj[NN * 2 * RPI_];   // per-object matched relation indices
__device__ int g_adj_cnt[NN];

// ---------------- fp16 plane scratch -----------------------------------------
__device__ __half g_Pa_h[RR * OBJD], g_Pa_l[RR * OBJD];
__device__ __half g_Pb_h[NN * OBJD], g_Pb_l[NN * OBJD];
__device__ __half g_Ps_h[RR * HD],  g_Ps_l[RR * HD];
__device__ __half g_Ph_h[RR * HD],  g_Ph_l[RR * HD];
__device__ __half g_Po1_h[NN * HD], g_Po1_l[NN * HD];
__device__ __half g_Po2_h[NN * HD], g_Po2_l[NN * HD];
__device__ __half g_Po3_h[NN * HD], g_Po3_l[NN * HD];
__device__ __half g_OP_h[NN * KEMB], g_OP_l[NN * KEMB];
// weight planes, [N,K]
__device__ __half g_Wop_h[HD * OBJD], g_Wop_l[HD * OBJD];
__device__ __half g_Wrp_h[HD * OBJD], g_Wrp_l[HD * OBJD];
__device__ __half g_Wemb_h[HD * KEMB], g_Wemb_l[HD * KEMB];
__device__ __half g_Wcb_h[3 * HD * HD], g_Wcb_l[3 * HD * HD];
__device__ __half g_Wct_h[3 * HD * HD], g_Wct_l[3 * HD * HD];
__device__ __half g_Ugr2_h[HD * HD],   g_Ugr2_l[HD * HD];
__device__ __half g_Wgo_h[3 * HD * HD], g_Wgo_l[3 * HD * HD];
__device__ __half g_Ugo_h[3 * HD * HD], g_Ugo_l[3 * HD * HD];
__device__ __half g_Wcr_h[128 * HD], g_Wcr_l[128 * HD];
__device__ __half g_Wco_h[256 * HD], g_Wco_l[256 * HD];

// ============================================================================
// fp16 3-pass GEMM body (hi/lo planes), ldmatrix fragments.
// mode 0: C = A@B^T (+bias) (+addm); optional planes; packN>0 -> scalar pack.
// mode 1: GRU-fin fusion (contiguous XW3 only).
// ============================================================================
#define HROW 20
#define HPLW (128 * HROW)
#define HSTW (4 * HPLW)
#define HG_SMEM (2 * HSTW * 4)

struct HGArgs {
    const __half *Ah, *Al, *Bh, *Bl;
    float* C; int ldc;
    int M, N, K;
    const float* bias;
    const float* addm;
    __half *Ch, *Cl;
    int mode;
    int packN;
    const float* XW3; int ldxw;
    const float* Z;
    float* Hh;
};

__device__ __forceinline__ void hgemm_body(const HGArgs& a, int blk) {
    extern __shared__ uint32_t sm[];
    const int tid = threadIdx.x;
    const int lane = tid & 31;
    const int warp = tid >> 5;
    const int wm = warp >> 2;
    const int wn = warp & 3;
    const int lr = lane >> 2;
    const int lc = lane & 3;
    const int nx = a.N >> 7;
    const int m0 = (blk / nx) * 128;
    const int n0 = (blk % nx) * 128;
    const int K = a.K;
    const int KT = K / 32;

    const uint32_t sbase = (uint32_t)__cvta_generic_to_shared(sm);
    const int aRowOff = (wm * 64 + (lane & 15)) * HROW + (lane >> 4) * 4;
    const int bRowOff = (wn * 32 + (lane & 7) + ((lane >> 4) << 3)) * HROW
                      + (((lane >> 3) & 1) * 4);

    const __half* Ah = a.Ah;
    const __half* Al = a.Al;
    const __half* Bh = a.Bh;
    const __half* Bl = a.Bl;

    auto load_stage = [&](int kt, int buf) {
        const int k0 = kt * 32;
        uint32_t sb = sbase + (uint32_t)(buf * HSTW * 4);
#pragma unroll
        for (int i = 0; i < 2; i++) {
            int cid = tid * 2 + i;
            int row = cid >> 2, ch = cid & 3;
            uint32_t d = sb + (uint32_t)((row * HROW + ch * 4) * 4);
            size_t src = (size_t)(m0 + row) * K + k0 + ch * 8;
            cp16(d, Ah + src);
            cp16(d + HPLW * 4, Al + src);
        }
#pragma unroll
        for (int i = 0; i < 2; i++) {
            int cid = tid * 2 + i;
            int row = cid >> 2, ch = cid & 3;
            uint32_t d = sb + (uint32_t)((2 * HPLW + row * HROW + ch * 4) * 4);
            size_t src = (size_t)(n0 + row) * K + k0 + ch * 8;
            cp16(d, Bh + src);
            cp16(d + HPLW * 4, Bl + src);
        }
        asm volatile("cp.async.commit_group;");
    };

    float acc[4][4][4];
#pragma unroll
    for (int i = 0; i < 4; i++)
#pragma unroll
        for (int j = 0; j < 4; j++)
#pragma unroll
            for (int l = 0; l < 4; l++) acc[i][j][l] = 0.f;

    load_stage(0, 0);
    if (KT > 1) load_stage(1, 1);
    asm volatile("cp.async.wait_group 1;");
    __syncthreads();

    for (int kt = 0; kt < KT; kt++) {
        const int cur = kt & 1;
        const uint32_t uA = sbase + (uint32_t)(cur * HSTW * 4);
        const uint32_t uB = uA + (uint32_t)(2 * HPLW * 4);

#pragma unroll
        for (int wc = 0; wc < 16; wc += 8) {
            uint32_t aH[4][4], aL[4][4], bH[4][2], bL[4][2];
#pragma unroll
            for (int mt = 0; mt < 4; mt++) {
                uint32_t ad = uA + (uint32_t)((aRowOff + mt * 16 * HROW + wc) * 4);
                LDSM_X4(aH[mt][0], aH[mt][1], aH[mt][2], aH[mt][3], ad);
                LDSM_X4(aL[mt][0], aL[mt][1], aL[mt][2], aL[mt][3], ad + HPLW * 4);
            }
#pragma unroll
            for (int pr = 0; pr < 2; pr++) {
                uint32_t bd = uB + (uint32_t)((bRowOff + pr * 16 * HROW + wc) * 4);
                LDSM_X4(bH[2 * pr][0], bH[2 * pr][1], bH[2 * pr + 1][0], bH[2 * pr + 1][1], bd);
                LDSM_X4(bL[2 * pr][0], bL[2 * pr][1], bL[2 * pr + 1][0], bL[2 * pr + 1][1],
                        bd + HPLW * 4);
            }
#pragma unroll
            for (int mt = 0; mt < 4; mt++)
#pragma unroll
                for (int nt = 0; nt < 4; nt++) {
                    mma_f16(acc[mt][nt], aH[mt], bH[nt]);
                    mma_f16(acc[mt][nt], aH[mt], bL[nt]);
                    mma_f16(acc[mt][nt], aL[mt], bH[nt]);
                }
        }
        __syncthreads();
        if (kt + 2 < KT) {
            load_stage(kt + 2, cur);
            asm volatile("cp.async.wait_group 1;");
        } else if (kt + 1 < KT) {
            asm volatile("cp.async.wait_group 0;");
        }
        __syncthreads();
    }

    if (a.mode == 0) {
        if (a.packN > 0) {
#pragma unroll
            for (int mt = 0; mt < 4; mt++) {
#pragma unroll
                for (int nt = 0; nt < 4; nt++) {
#pragma unroll
                    for (int v = 0; v < 4; v++) {
                        int gm = m0 + wm * 64 + mt * 16 + lr + (v >> 1) * 8;
                        int gn = n0 + wn * 32 + nt * 8 + lc * 2 + (v & 1);
                        if (gn < a.packN)
                            a.C[(size_t)gm * a.ldc + gn] = acc[mt][nt][v] + a.bias[gn];
                    }
                }
            }
        } else {
#pragma unroll
            for (int mt = 0; mt < 4; mt++) {
                int gm0 = m0 + wm * 64 + mt * 16 + lr;
                int gm1 = gm0 + 8;
#pragma unroll
                for (int nt = 0; nt < 4; nt++) {
                    int gn = n0 + wn * 32 + nt * 8 + lc * 2;
                    float b0 = 0.f, b1 = 0.f;
                    if (a.bias) { b0 = a.bias[gn]; b1 = a.bias[gn + 1]; }
                    float2 v0 = make_float2(acc[mt][nt][0] + b0, acc[mt][nt][1] + b1);
                    float2 v1 = make_float2(acc[mt][nt][2] + b0, acc[mt][nt][3] + b1);
                    if (a.addm) {
                        float2 m0v = *(const float2*)(a.addm + (size_t)gm0 * a.ldc + gn);
                        float2 m1v = *(const float2*)(a.addm + (size_t)gm1 * a.ldc + gn);
                        v0.x += m0v.x; v0.y += m0v.y;
                        v1.x += m1v.x; v1.y += m1v.y;
                    }
                    *(float2*)(a.C + (size_t)gm0 * a.ldc + gn) = v0;
                    *(float2*)(a.C + (size_t)gm1 * a.ldc + gn) = v1;
                    if (a.Ch) {
                        __half hx, lx, hy, ly;
                        split_h(v0.x, hx, lx); split_h(v0.y, hy, ly);
                        *(__half2*)(a.Ch + (size_t)gm0 * a.ldc + gn) = __halves2half2(hx, hy);
                        *(__half2*)(a.Cl + (size_t)gm0 * a.ldc + gn) = __halves2half2(lx, ly);
                        split_h(v1.x, hx, lx); split_h(v1.y, hy, ly);
                        *(__half2*)(a.Ch + (size_t)gm1 * a.ldc + gn) = __halves2half2(hx, hy);
                        *(__half2*)(a.Cl + (size_t)gm1 * a.ldc + gn) = __halves2half2(lx, ly);
                    }
                }
            }
        }
    } else {
        // GRU-fin: n = tanh(acc + XW3 + b); h = (1-z)h + z n
#pragma unroll
        for (int mt = 0; mt < 4; mt++) {
#pragma unroll
            for (int nt = 0; nt < 4; nt++) {
#pragma unroll
                for (int v = 0; v < 4; v++) {
                    int gm = m0 + wm * 64 + mt * 16 + lr + (v >> 1) * 8;
                    int gn = n0 + wn * 32 + nt * 8 + lc * 2 + (v & 1);
                    size_t off = (size_t)gm * a.ldc + gn;
                    float n = tanhf(acc[mt][nt][v] + a.XW3[(size_t)gm * a.ldxw + gn]
                                    + a.bias[gn]);
                    float z = a.Z[off];
                    float h = (1.f - z) * a.Hh[off] + z * n;
                    a.Hh[off] = h;
                    __half ph, pl;
                    split_h(h, ph, pl);
                    a.Ch[off] = ph;
                    a.Cl[off] = pl;
                }
            }
        }
    }
}

__global__ __launch_bounds__(256, 2) void hgemm_kernel(HGArgs a) {
    hgemm_body(a, blockIdx.x);
}
__global__ __launch_bounds__(256, 2) void hgemm_dual_kernel(HGArgs a, HGArgs b, int na) {
    int bx = blockIdx.x;
    if (bx < na) hgemm_body(a, bx);
    else hgemm_body(b, bx - na);
}
__global__ __launch_bounds__(256, 2) void hgemm_tri_kernel(HGArgs a, HGArgs b, HGArgs c,
                                                           int na, int nab) {
    int bx = blockIdx.x;
    if (bx < na) hgemm_body(a, bx);
    else if (bx < nab) hgemm_body(b, bx - na);
    else hgemm_body(c, bx - nab);
}

// ---------------- split kernels ---------------------------------------------
__global__ void asplit_kernel(const float2* __restrict__ in,
                              __half2* __restrict__ hi, __half2* __restrict__ lo, int n2) {
    int i = blockIdx.x * blockDim.x + threadIdx.x;
    if (i >= n2) return;
    float2 v = in[i];
    __half hx, lx, hy, ly;
    split_h(v.x, hx, lx);
    split_h(v.y, hy, ly);
    hi[i] = __halves2half2(hx, hy);
    lo[i] = __halves2half2(lx, ly);
}

__global__ void wsplit_kernel(const float* __restrict__ W, int ldw, int c0, int wcols, int wrows,
                              __half* __restrict__ Th, __half* __restrict__ Tl, int K) {
    __shared__ float t[32][33];
    int kb = blockIdx.y * 32, nb = blockIdx.x * 32;
    int tx = threadIdx.x, ty = threadIdx.y;
    int col = c0 + nb + tx;
#pragma unroll
    for (int i = 0; i < 32; i += 8) {
        int kr = kb + ty + i;
        t[ty + i][tx] = (col < wcols && kr < wrows) ? W[(size_t)kr * ldw + col] : 0.f;
    }
    __syncthreads();
#pragma unroll
    for (int i = 0; i < 32; i += 8) {
        int n = nb + ty + i, k = kb + tx;
        __half h, l;
        split_h(t[tx][ty + i], h, l);
        Th[(size_t)n * K + k] = h;
        Tl[(size_t)n * K + k] = l;
    }
}

__global__ void biaspad_kernel(const float* __restrict__ b, float* __restrict__ out,
                               int n, int npad) {
    int i = blockIdx.x * blockDim.x + threadIdx.x;
    if (i < npad) out[i] = (i < n) ? b[i] : 0.f;
}

// ---------------- generic fp32 SGEMM (WCOMB only) -----------------------------
__global__ __launch_bounds__(256) void sgemm_kernel(
    const float* __restrict__ A, int lda,
    const float* __restrict__ B, int ldb,
    float* __restrict__ C, int ldc,
    int M, int N, int K)
{
    __shared__ float As[8][132];
    __shared__ float Bs[8][128];
    const int tid = threadIdx.x;
    const int tx = tid & 15;
    const int ty = tid >> 4;
    const int m0 = blockIdx.y * 128;
    const int n0 = blockIdx.x * 128;

    float acc[8][8];
#pragma unroll
    for (int i = 0; i < 8; i++)
#pragma unroll
        for (int j = 0; j < 8; j++) acc[i][j] = 0.f;

    for (int k0 = 0; k0 < K; k0 += 8) {
#pragma unroll
        for (int l = 0; l < 4; l++) {
            int e = tid + l * 256;
            int r = e >> 3, c = e & 7;
            float v = 0.f;
            int gm = m0 + r, gk = k0 + c;
            if (gm < M && gk < K) v = A[(size_t)gm * lda + gk];
            As[c][r] = v;
        }
#pragma unroll
        for (int l = 0; l < 4; l++) {
            int e = tid + l * 256;
            int r = e >> 7, c = e & 127;
            float v = 0.f;
            int gk = k0 + r, gn = n0 + c;
            if (gk < K && gn < N) v = B[(size_t)gk * ldb + gn];
            Bs[r][c] = v;
        }
        __syncthreads();
#pragma unroll
        for (int k = 0; k < 8; k++) {
            float a[8], b[8];
#pragma unroll
            for (int i = 0; i < 8; i++) a[i] = As[k][ty * 8 + i];
#pragma unroll
            for (int j = 0; j < 8; j++) b[j] = Bs[k][tx * 8 + j];
#pragma unroll
            for (int i = 0; i < 8; i++)
#pragma unroll
                for (int j = 0; j < 8; j++)
                    acc[i][j] = fmaf(a[i], b[j], acc[i][j]);
        }
        __syncthreads();
    }
#pragma unroll
    for (int i = 0; i < 8; i++) {
        int gm = m0 + ty * 8 + i;
        if (gm >= M) continue;
#pragma unroll
        for (int j = 0; j < 8; j++) {
            int gn = n0 + tx * 8 + j;
            if (gn >= N) continue;
            C[(size_t)gm * ldc + gn] = acc[i][j];
        }
    }
}

// ---------------- decode rel_inds --------------------------------------------
__global__ __launch_bounds__(1024) void decode_rel_kernel(const void* rel_raw) {
    __shared__ int s_or;
    int tid = threadIdx.x;
    if (tid == 0) s_or = 0;
    __syncthreads();
    const int* v32 = (const int*)rel_raw;
    int acc = 0;
    for (int i = tid; i < (3 * RR) / 2; i += 1024) acc |= v32[2 * i + 1];
    if (acc) atomicOr(&s_or, 1);
    __syncthreads();
    bool is64 = (s_or == 0);
    if (is64) {
        const long long* v = (const long long*)rel_raw;
        for (int r = tid; r < RR; r += 1024) {
            g_s_idx[r] = (int)v[3 * r + 1];
            g_o_idx[r] = (int)v[3 * r + 2];
        }
    } else {
        for (int r = tid; r < RR; r += 1024) {
            g_s_idx[r] = v32[3 * r + 1];
            g_o_idx[r] = v32[3 * r + 2];
        }
    }
}

// ---------------- per-object adjacency (deterministic order) ------------------
__global__ void build_adj_kernel() {
    int obj = blockIdx.x * blockDim.x + threadIdx.x;
    if (obj >= NN) return;
    int img = obj >> 6;
    int base = img * RPI_;
    int* lst = g_adj + (size_t)obj * 2 * RPI_;
    int cnt = 0;
    for (int j = 0; j < RPI_; j++) {
        int rel = base + j;
        if (g_s_idx[rel] == obj) lst[cnt++] = rel;
        if (g_o_idx[rel] == obj) lst[cnt++] = rel;
    }
    g_adj_cnt[obj] = cnt;
}

// ---------------- softmax -> padded fp16 planes -------------------------------
__global__ void softmax_split_kernel(const float* __restrict__ X,
                                     __half* __restrict__ Ph, __half* __restrict__ Pl) {
    int row = blockIdx.x;
    int tid = threadIdx.x;
    __shared__ float red[256];
    const float* x = X + (size_t)row * NOC_;
    float m = -3.4e38f;
    for (int c = tid; c < NOC_; c += 256) m = fmaxf(m, x[c]);
    red[tid] = m; __syncthreads();
    for (int s = 128; s > 0; s >>= 1) {
        if (tid < s) red[tid] = fmaxf(red[tid], red[tid + s]);
        __syncthreads();
    }
    m = red[0]; __syncthreads();
    float sum = 0.f;
    for (int c = tid; c < NOC_; c += 256) sum += expf(x[c] - m);
    red[tid] = sum; __syncthreads();
    for (int s = 128; s > 0; s >>= 1) {
        if (tid < s) red[tid] += red[tid + s];
        __syncthreads();
    }
    float inv = 1.f / red[0];
    for (int c = tid; c < KEMB; c += 256) {
        float v = (c < NOC_) ? expf(x[c] - m) * inv : 0.f;
        __half h, l;
        split_h(v, h, l);
        Ph[(size_t)row * KEMB + c] = h;
        Pl[(size_t)row * KEMB + c] = l;
    }
}

__global__ void softmax_kernel(const float* __restrict__ X, float* __restrict__ Y) {
    int row = blockIdx.x;
    int tid = threadIdx.x;
    __shared__ float red[256];
    const float* x = X + (size_t)row * NOC_;
    float m = -3.4e38f;
    for (int c = tid; c < NOC_; c += 256) m = fmaxf(m, x[c]);
    red[tid] = m; __syncthreads();
    for (int s = 128; s > 0; s >>= 1) {
        if (tid < s) red[tid] = fmaxf(red[tid], red[tid + s]);
        __syncthreads();
    }
    m = red[0]; __syncthreads();
    float sum = 0.f;
    for (int c = tid; c < NOC_; c += 256) sum += expf(x[c] - m);
    red[tid] = sum; __syncthreads();
    for (int s = 128; s > 0; s >>= 1) {
        if (tid < s) red[tid] += red[tid + s];
        __syncthreads();
    }
    float inv = 1.f / red[0];
    for (int c = tid; c < NOC_; c += 256)
        Y[(size_t)row * NOC_ + c] = expf(x[c] - m) * inv;
}

// ---------------- XWR[r] = HW[s_r] + HW[o_r]  (float4) ------------------------
__global__ void xwr_gather_kernel(const float4* __restrict__ HW, float4* __restrict__ XWR) {
    int i = blockIdx.x * blockDim.x + threadIdx.x;
    if (i >= RR * 384) return;
    int r = i / 384;
    int c = i - r * 384;
    float4 a = HW[g_s_idx[r] * 384 + c];
    float4 b = HW[g_o_idx[r] * 384 + c];
    XWR[i] = make_float4(a.x + b.x, a.y + b.y, a.z + b.z, a.w + b.w);
}

// ---------------- m_obj scatter via adjacency lists ---------------------------
__global__ __launch_bounds__(512) void scatter_obj_kernel(const float* __restrict__ HM, int ldhm,
                                                          __half* __restrict__ Mh,
                                                          __half* __restrict__ Ml) {
    int obj = blockIdx.x;
    int c = threadIdx.x;
    int cnt = g_adj_cnt[obj];
    const int* lst = g_adj + (size_t)obj * 2 * RPI_;
    float acc = 0.f;
    for (int k = 0; k < cnt; k++) {
        int rel = __ldg(lst + k);
        acc += HM[(size_t)rel * ldhm + c];
    }
    __half h, l;
    split_h(acc, h, l);
    Mh[(size_t)obj * HD + c] = h;
    Ml[(size_t)obj * HD + c] = l;
}

// ---------------- GRU z, r*h -> planes ----------------------------------------
__global__ void gru_zr_kernel(const float* __restrict__ XW, int ldxw,
                              const float* __restrict__ HU, int ldhu,
                              const float* __restrict__ b, const float* __restrict__ Hh,
                              float* __restrict__ Z,
                              __half* __restrict__ RHh, __half* __restrict__ RHl, int M) {
    int idx = blockIdx.x * blockDim.x + threadIdx.x;
    if (idx >= M * HD) return;
    int row = idx >> 9;
    int c = idx & 511;
    float z = XW[(size_t)row * ldxw + c] + HU[(size_t)row * ldhu + c] + b[c];
    float r = XW[(size_t)row * ldxw + 512 + c] + HU[(size_t)row * ldhu + 512 + c] + b[512 + c];
    z = 1.f / (1.f + expf(-z));
    r = 1.f / (1.f + expf(-r));
    Z[idx] = z;
    __half h, l;
    split_h(r * Hh[idx], h, l);
    RHh[idx] = h; RHl[idx] = l;
}

// ---------------- NMS ----------------------------------------------------------
__global__ __launch_bounds__(512) void nms_kernel(const float* __restrict__ SP,
                                                  const float* __restrict__ BOX,
                                                  unsigned char* __restrict__ KEEP) {
    int cls = blockIdx.x + 1;
    int tid = threadIdx.x;
    __shared__ float sc[NN];
    __shared__ int sidx[NN];
    __shared__ float bx[NN][4];
    __shared__ float area[NN];
    __shared__ unsigned char keep[NN];

    sc[tid] = SP[(size_t)tid * NOC_ + cls];
    sidx[tid] = tid;
    __syncthreads();

    for (int k = 2; k <= NN; k <<= 1) {
        for (int j = k >> 1; j > 0; j >>= 1) {
            int ixj = tid ^ j;
            if (ixj > tid) {
                float s1 = sc[tid], s2 = sc[ixj];
                int i1 = sidx[tid], i2 = sidx[ixj];
                bool dir = ((tid & k) == 0);
                bool precBA = (s2 > s1) || (s2 == s1 && i2 < i1);
                if (precBA == dir) {
                    sc[tid] = s2; sc[ixj] = s1;
                    sidx[tid] = i2; sidx[ixj] = i1;
                }
            }
            __syncthreads();
        }
    }

    int oi = sidx[tid];
    float x1 = BOX[((size_t)oi * NOC_ + cls) * 4 + 0];
    float y1 = BOX[((size_t)oi * NOC_ + cls) * 4 + 1];
    float x2 = BOX[((size_t)oi * NOC_ + cls) * 4 + 2];
    float y2 = BOX[((size_t)oi * NOC_ + cls) * 4 + 3];
    bx[tid][0] = x1; bx[tid][1] = y1; bx[tid][2] = x2; bx[tid][3] = y2;
    area[tid] = (x2 - x1) * (y2 - y1);
    keep[tid] = 1;
    __syncthreads();

    for (int i = 0; i < NN - 1; i++) {
        if (tid > i && keep[i] && keep[tid]) {
            float lx = fmaxf(bx[i][0], x1);
            float ly = fmaxf(bx[i][1], y1);
            float rx = fminf(bx[i][2], x2);
            float ry = fminf(bx[i][3], y2);
            float w = fmaxf(rx - lx, 0.f);
            float h = fmaxf(ry - ly, 0.f);
            float inter = w * h;
            float iou = inter / (area[i] + area[tid] - inter + 1e-9f);
            if (iou > IOU_THR_) keep[tid] = 0;
        }
        __syncthreads();
    }
    KEEP[(size_t)(cls - 1) * NN + oi] = keep[tid];
}

// ---------------- obj_preds -----------------------------------------------------
__global__ void preds_kernel(const float* __restrict__ SP, const unsigned char* __restrict__ KEEP,
                             float* __restrict__ out) {
    int n = blockIdx.x * blockDim.x + threadIdx.x;
    if (n >= NN) return;
    float best = -1.f;
    int bi = 0;
    for (int c = 0; c < 150; c++) {
        float v = KEEP[(size_t)c * NN + n] ? SP[(size_t)n * NOC_ + c + 1] : 0.f;
        if (v > best) { best = v; bi = c; }
    }
    out[n] = (float)(bi + 1);
}

// ---------------- host orchestration --------------------------------------------
struct Scratch {
    float *FO, *HOBJ, *HREL, *XWR, *HMHU, *HW, *ZR;
    float *XWO, *HUO, *ZO, *SP, *WCOMB, *BCR, *BCO;
    unsigned char* KEEP;
    __half *Pa_h, *Pa_l, *Pb_h, *Pb_l, *Ps_h, *Ps_l, *Ph_h, *Ph_l;
    __half *Po1_h, *Po1_l, *Po2_h, *Po2_l, *Po3_h, *Po3_l, *OP_h, *OP_l;
    __half *Wop_h, *Wop_l, *Wrp_h, *Wrp_l, *Wemb_h, *Wemb_l;
    __half *Wcb_h, *Wcb_l, *Wct_h, *Wct_l;
    __half *Ugr2_h, *Ugr2_l, *Wgo_h, *Wgo_l, *Ugo_h, *Ugo_l;
    __half *Wcr_h, *Wcr_l, *Wco_h, *Wco_l;
    bool init = false;
};
static Scratch g_sc;

static void init_scratch() {
    if (g_sc.init) return;
    void* p;
#define GET(sym, fld, T) cudaGetSymbolAddress(&p, sym); g_sc.fld = (T*)p;
    GET(g_fo, FO, float)
    GET(g_h_obj, HOBJ, float)
    GET(g_h_rel, HREL, float)
    GET(g_xw_rel, XWR, float)
    GET(g_hmhu, HMHU, float)
    GET(g_hw, HW, float)
    GET(g_z_rel, ZR, float)
    GET(g_xw_obj, XWO, float)
    GET(g_hu_obj, HUO, float)
    GET(g_z_obj, ZO, float)
    GET(g_sp, SP, float)
    GET(g_wcomb, WCOMB, float)
    GET(g_bcr, BCR, float)
    GET(g_bco, BCO, float)
    GET(g_keep, KEEP, unsigned char)
    GET(g_Pa_h, Pa_h, __half) GET(g_Pa_l, Pa_l, __half)
    GET(g_Pb_h, Pb_h, __half) GET(g_Pb_l, Pb_l, __half)
    GET(g_Ps_h, Ps_h, __half) GET(g_Ps_l, Ps_l, __half)
    GET(g_Ph_h, Ph_h, __half) GET(g_Ph_l, Ph_l, __half)
    GET(g_Po1_h, Po1_h, __half) GET(g_Po1_l, Po1_l, __half)
    GET(g_Po2_h, Po2_h, __half) GET(g_Po2_l, Po2_l, __half)
    GET(g_Po3_h, Po3_h, __half) GET(g_Po3_l, Po3_l, __half)
    GET(g_OP_h, OP_h, __half)  GET(g_OP_l, OP_l, __half)
    GET(g_Wop_h, Wop_h, __half) GET(g_Wop_l, Wop_l, __half)
    GET(g_Wrp_h, Wrp_h, __half) GET(g_Wrp_l, Wrp_l, __half)
    GET(g_Wemb_h, Wemb_h, __half) GET(g_Wemb_l, Wemb_l, __half)
    GET(g_Wcb_h, Wcb_h, __half) GET(g_Wcb_l, Wcb_l, __half)
    GET(g_Wct_h, Wct_h, __half) GET(g_Wct_l, Wct_l, __half)
    GET(g_Ugr2_h, Ugr2_h, __half) GET(g_Ugr2_l, Ugr2_l, __half)
    GET(g_Wgo_h, Wgo_h, __half) GET(g_Wgo_l, Wgo_l, __half)
    GET(g_Ugo_h, Ugo_h, __half) GET(g_Ugo_l, Ugo_l, __half)
    GET(g_Wcr_h, Wcr_h, __half) GET(g_Wcr_l, Wcr_l, __half)
    GET(g_Wco_h, Wco_h, __half) GET(g_Wco_l, Wco_l, __half)
#undef GET
    cudaFuncSetAttribute(hgemm_kernel, cudaFuncAttributeMaxDynamicSharedMemorySize, HG_SMEM);
    cudaFuncSetAttribute(hgemm_dual_kernel, cudaFuncAttributeMaxDynamicSharedMemorySize, HG_SMEM);
    cudaFuncSetAttribute(hgemm_tri_kernel, cudaFuncAttributeMaxDynamicSharedMemorySize, HG_SMEM);
    g_sc.init = true;
}

static HGArgs mkargs(const __half* Ah, const __half* Al, const __half* Bh, const __half* Bl,
                     float* C, int ldc, int M, int N, int K, const float* bias,
                     __half* Ch = nullptr, __half* Cl = nullptr) {
    HGArgs a;
    a.Ah = Ah; a.Al = Al; a.Bh = Bh; a.Bl = Bl;
    a.C = C; a.ldc = ldc; a.M = M; a.N = N; a.K = K;
    a.bias = bias; a.addm = nullptr; a.Ch = Ch; a.Cl = Cl;
    a.mode = 0; a.packN = 0;
    a.XW3 = nullptr; a.ldxw = 0; a.Z = nullptr; a.Hh = nullptr;
    return a;
}

static int nblk(const HGArgs& a) { return (a.M / 128) * (a.N / 128); }
static void hgemm1(const HGArgs& a) {
    hgemm_kernel<<<nblk(a), 256, HG_SMEM>>>(a);
}
static void hgemm2(const HGArgs& a, const HGArgs& b) {
    hgemm_dual_kernel<<<nblk(a) + nblk(b), 256, HG_SMEM>>>(a, b, nblk(a));
}
static void hgemm3(const HGArgs& a, const HGArgs& b, const HGArgs& c) {
    int na = nblk(a), nab = na + nblk(b);
    hgemm_tri_kernel<<<nab + nblk(c), 256, HG_SMEM>>>(a, b, c, na, nab);
}

static void asplit(const float* A, __half* hi, __half* lo, int n) {
    int n2 = n / 2;
    asplit_kernel<<<(n2 + 255) / 256, 256>>>((const float2*)A, (__half2*)hi, (__half2*)lo, n2);
}

static void wsplit(const float* W, int ldw, int c0, int wcols, int wrows,
                   __half* Th, __half* Tl, int K, int ncols) {
    dim3 g(ncols / 32, K / 32);
    wsplit_kernel<<<g, dim3(32, 8)>>>(W, ldw, c0, wcols, wrows, Th, Tl, K);
}

extern "C" void kernel_launch(void* const* d_in, const int* in_sizes, int n_in,
                              void* d_out, int out_size) {
    (void)in_sizes; (void)n_in; (void)out_size;
    init_scratch();

    const float* obj_fmaps  = (const float*)d_in[1];
    const float* obj_logits = (const float*)d_in[2];
    const void*  rel_raw    = d_in[3];
    const float* vr         = (const float*)d_in[4];
    const float* boxes      = (const float*)d_in[5];
    const float* W_obj_proj = (const float*)d_in[6];
    const float* b_obj_proj = (const float*)d_in[7];
    const float* W_rel_proj = (const float*)d_in[8];
    const float* b_rel_proj = (const float*)d_in[9];
    const float* W_emb      = (const float*)d_in[10];
    const float* W_msg_rel  = (const float*)d_in[11];
    const float* W_msg_obj  = (const float*)d_in[12];
    const float* W_gru_obj  = (const float*)d_in[13];
    const float* U_gru_obj  = (const float*)d_in[14];
    const float* b_gru_obj  = (const float*)d_in[15];
    const float* W_gru_rel  = (const float*)d_in[16];
    const float* U_gru_rel  = (const float*)d_in[17];
    const float* b_gru_rel  = (const float*)d_in[18];
    const float* W_cls_rel  = (const float*)d_in[19];
    const float* b_cls_rel  = (const float*)d_in[20];
    const float* W_cls_obj  = (const float*)d_in[21];
    const float* b_cls_obj  = (const float*)d_in[22];

    float* out_obj_logits = (float*)d_out;
    float* out_preds      = out_obj_logits + NN * NOC_;
    float* out_rel_logits = out_preds + NN;

    // 0. decode + adjacency; weight planes
    decode_rel_kernel<<<1, 1024>>>(rel_raw);
    build_adj_kernel<<<2, 256>>>();
    wsplit(W_obj_proj, HD, 0, HD, OBJD, g_sc.Wop_h, g_sc.Wop_l, OBJD, HD);
    wsplit(W_rel_proj, HD, 0, HD, OBJD, g_sc.Wrp_h, g_sc.Wrp_l, OBJD, HD);
    wsplit(W_emb, HD, 0, HD, NOC_, g_sc.Wemb_h, g_sc.Wemb_l, KEMB, HD);
    wsplit(W_msg_obj, HD, 0, HD, HD, g_sc.Wct_h, g_sc.Wct_l, HD, HD);
    wsplit(U_gru_rel, 3 * HD, 0, 3 * HD, HD, g_sc.Wct_h + (size_t)HD * HD,
           g_sc.Wct_l + (size_t)HD * HD, HD, 2 * HD);
    wsplit(U_gru_rel, 3 * HD, 2 * HD, 3 * HD, HD, g_sc.Ugr2_h, g_sc.Ugr2_l, HD, HD);
    wsplit(W_gru_obj, 3 * HD, 0, 3 * HD, HD, g_sc.Wgo_h, g_sc.Wgo_l, HD, 3 * HD);
    wsplit(U_gru_obj, 3 * HD, 0, 3 * HD, HD, g_sc.Ugo_h, g_sc.Ugo_l, HD, 3 * HD);
    wsplit(W_cls_rel, NRC_, 0, NRC_, HD, g_sc.Wcr_h, g_sc.Wcr_l, HD, 128);
    wsplit(W_cls_obj, NOC_, 0, NOC_, HD, g_sc.Wco_h, g_sc.Wco_l, HD, 256);
    biaspad_kernel<<<1, 128>>>(b_cls_rel, g_sc.BCR, NRC_, 128);
    biaspad_kernel<<<1, 256>>>(b_cls_obj, g_sc.BCO, NOC_, 256);
    {
        dim3 g((3 * HD + 127) / 128, (HD + 127) / 128);
        sgemm_kernel<<<g, 256>>>(W_msg_rel, HD, W_gru_rel, 3 * HD, g_sc.WCOMB, 3 * HD,
                                 HD, 3 * HD, HD);
    }
    wsplit(g_sc.WCOMB, 3 * HD, 0, 3 * HD, HD, g_sc.Wcb_h, g_sc.Wcb_l, HD, 3 * HD);

    // 1. activation splits
    asplit(obj_fmaps, g_sc.Pb_h, g_sc.Pb_l, NN * OBJD);
    asplit(vr, g_sc.Pa_h, g_sc.Pa_l, RR * OBJD);
    softmax_split_kernel<<<NN, 256>>>(obj_logits, g_sc.OP_h, g_sc.OP_l);

    // 2. fo + h_rel (paired)
    hgemm2(mkargs(g_sc.Pb_h, g_sc.Pb_l, g_sc.Wop_h, g_sc.Wop_l, g_sc.FO, HD,
                  NN, HD, OBJD, b_obj_proj),
           mkargs(g_sc.Pa_h, g_sc.Pa_l, g_sc.Wrp_h, g_sc.Wrp_l, g_sc.HREL, HD,
                  RR, HD, OBJD, b_rel_proj, g_sc.Ph_h, g_sc.Ph_l));

    // 3. h_obj = obj_probs @ W_emb + fo
    {
        HGArgs a = mkargs(g_sc.OP_h, g_sc.OP_l, g_sc.Wemb_h, g_sc.Wemb_l, g_sc.HOBJ, HD,
                          NN, HD, KEMB, nullptr, g_sc.Po2_h, g_sc.Po2_l);
        a.addm = g_sc.FO;
        hgemm1(a);
    }

    const int EW_REL = (RR * HD + 255) / 256;
    const int EW_OBJ = (NN * HD + 255) / 256;
    const int XG_BLOCKS = (RR * 384 + 255) / 256;
    const __half* Ugo2_h = g_sc.Ugo_h + (size_t)2 * HD * HD;
    const __half* Ugo2_l = g_sc.Ugo_l + (size_t)2 * HD * HD;

    for (int t = 0; t < TSTEPS; t++) {
        // HW = HOBJ@WCOMB ; HMHU = h_rel@WCAT ; HUO = HOBJ@Ugo01  (one tri launch)
        hgemm3(mkargs(g_sc.Po2_h, g_sc.Po2_l, g_sc.Wcb_h, g_sc.Wcb_l, g_sc.HW, 3 * HD,
                      NN, 3 * HD, HD, nullptr),
               mkargs(g_sc.Ph_h, g_sc.Ph_l, g_sc.Wct_h, g_sc.Wct_l, g_sc.HMHU, 3 * HD,
                      RR, 3 * HD, HD, nullptr),
               mkargs(g_sc.Po2_h, g_sc.Po2_l, g_sc.Ugo_h, g_sc.Ugo_l, g_sc.HUO, 2 * HD,
                      NN, 2 * HD, HD, nullptr));
        // XWR[r] = HW[s_r] + HW[o_r]
        xwr_gather_kernel<<<XG_BLOCKS, 256>>>((const float4*)g_sc.HW, (float4*)g_sc.XWR);
        scatter_obj_kernel<<<NN, 512>>>(g_sc.HMHU, 3 * HD, g_sc.Po1_h, g_sc.Po1_l);

        // GRU rel zr; then (rel NU+fin) paired with XWO
        gru_zr_kernel<<<EW_REL, 256>>>(g_sc.XWR, 3 * HD, g_sc.HMHU + HD, 3 * HD,
                                       b_gru_rel, g_sc.HREL, g_sc.ZR, g_sc.Ps_h, g_sc.Ps_l, RR);
        {
            HGArgs fin = mkargs(g_sc.Ps_h, g_sc.Ps_l, g_sc.Ugr2_h, g_sc.Ugr2_l,
                                nullptr, HD, RR, HD, HD, b_gru_rel + 2 * HD,
                                g_sc.Ph_h, g_sc.Ph_l);
            fin.mode = 1; fin.XW3 = g_sc.XWR + 2 * HD; fin.ldxw = 3 * HD;
            fin.Z = g_sc.ZR; fin.Hh = g_sc.HREL;
            hgemm2(fin,
                   mkargs(g_sc.Po1_h, g_sc.Po1_l, g_sc.Wgo_h, g_sc.Wgo_l, g_sc.XWO, 3 * HD,
                          NN, 3 * HD, HD, nullptr));
        }

        // GRU obj zr; NU+fin
        gru_zr_kernel<<<EW_OBJ, 256>>>(g_sc.XWO, 3 * HD, g_sc.HUO, 2 * HD,
                                       b_gru_obj, g_sc.HOBJ, g_sc.ZO, g_sc.Po3_h, g_sc.Po3_l, NN);
        {
            HGArgs fin = mkargs(g_sc.Po3_h, g_sc.Po3_l, Ugo2_h, Ugo2_l,
                                nullptr, HD, NN, HD, HD, b_gru_obj + 2 * HD,
                                g_sc.Po2_h, g_sc.Po2_l);
            fin.mode = 1; fin.XW3 = g_sc.XWO + 2 * HD; fin.ldxw = 3 * HD;
            fin.Z = g_sc.ZO; fin.Hh = g_sc.HOBJ;
            hgemm1(fin);
        }
    }

    // classifiers write straight into d_out (packN scalar stores)
    {
        HGArgs rc = mkargs(g_sc.Ph_h, g_sc.Ph_l, g_sc.Wcr_h, g_sc.Wcr_l,
                           out_rel_logits, NRC_, RR, 128, HD, g_sc.BCR);
        rc.packN = NRC_;
        HGArgs oc = mkargs(g_sc.Po2_h, g_sc.Po2_l, g_sc.Wco_h, g_sc.Wco_l,
                           out_obj_logits, NOC_, NN, 256, HD, g_sc.BCO);
        oc.packN = NOC_;
        hgemm2(rc, oc);
    }

    // softmax -> NMS -> preds
    softmax_kernel<<<NN, 256>>>(out_obj_logits, g_sc.SP);
    nms_kernel<<<150, 512>>>(g_sc.SP, boxes, g_sc.KEEP);
    preds_kernel<<<(NN + 255) / 256, 256>>>(g_sc.SP, g_sc.KEEP, out_preds);
}

// round 16
// speedup vs baseline: 1.1923x; 1.0158x over previous
#include <cuda_runtime.h>
#include <cuda_bf16.h>
#include <cuda_fp16.h>
#include <math.h>
#include <stdint.h>

// ---------------- problem constants ----------------
#define BIMG 8
#define OPI_ 64
#define RPI_ 1024
#define NN 512
#define RR 8192
#define OBJD 4096
#define HD 512
#define NOC_ 151
#define NRC_ 51
#define TSTEPS 3
#define IOU_THR_ 0.3f
#define KEMB 160

// ---------------- helpers ----------------------------------------------------
__device__ __forceinline__ void split_h(float v, __half& hi, __half& lo) {
    hi = __float2half_rn(v);
    lo = __float2half_rn(v - __half2float(hi));
}
__device__ __forceinline__ void mma_f16(float* c, const uint32_t* a, const uint32_t* b) {
    asm volatile(
        "mma.sync.aligned.m16n8k16.row.col.f32.f16.f16.f32 "
        "{%0,%1,%2,%3},{%4,%5,%6,%7},{%8,%9},{%0,%1,%2,%3};"
        : "+f"(c[0]), "+f"(c[1]), "+f"(c[2]), "+f"(c[3])
        : "r"(a[0]), "r"(a[1]), "r"(a[2]), "r"(a[3]), "r"(b[0]), "r"(b[1]));
}
__device__ __forceinline__ void cp16(uint32_t dst, const void* src) {
    asm volatile("cp.async.cg.shared.global [%0], [%1], 16;" :: "r"(dst), "l"(src));
}
#define LDSM_X4(r0, r1, r2, r3, addr) \
    asm volatile("ldmatrix.sync.aligned.m8n8.x4.shared.b16 {%0,%1,%2,%3}, [%4];" \
        : "=r"(r0), "=r"(r1), "=r"(r2), "=r"(r3) : "r"(addr))

// ---------------- f32 scratch ------------------------------------------------
__device__ float g_fo[NN * HD];
__device__ float g_h_obj[NN * HD];
__device__ float g_h_rel[RR * HD];
__device__ float g_xwr3[RR * HD];          // compact n-part of gathered XWR
__device__ float g_hmhu[RR * 3 * HD];
__device__ float g_hw[NN * 3 * HD];
__device__ float g_z_rel[RR * HD];
__device__ float g_xw_obj[NN * 3 * HD];
__device__ float g_hu_obj[NN * 2 * HD];
__device__ float g_z_obj[NN * HD];
__device__ float g_sp[NN * NOC_];
__device__ float g_wcomb[HD * 3 * HD];
__device__ float g_bcr[128];
__device__ float g_bco[256];
__device__ unsigned char g_keep[150 * NN];
__device__ int g_s_idx[RR];
__device__ int g_o_idx[RR];
__device__ int g_adj[NN * 2 * RPI_];
__device__ int g_adj_cnt[NN];

// ---------------- fp16 plane scratch -----------------------------------------
__device__ __half g_Pa_h[RR * OBJD], g_Pa_l[RR * OBJD];
__device__ __half g_Pb_h[NN * OBJD], g_Pb_l[NN * OBJD];
__device__ __half g_Ps_h[RR * HD],  g_Ps_l[RR * HD];
__device__ __half g_Ph_h[RR * HD],  g_Ph_l[RR * HD];
__device__ __half g_Po1_h[NN * HD], g_Po1_l[NN * HD];
__device__ __half g_Po2_h[NN * HD], g_Po2_l[NN * HD];
__device__ __half g_Po3_h[NN * HD], g_Po3_l[NN * HD];
__device__ __half g_OP_h[NN * KEMB], g_OP_l[NN * KEMB];
// weight planes, [N,K]
__device__ __half g_Wop_h[HD * OBJD], g_Wop_l[HD * OBJD];
__device__ __half g_Wrp_h[HD * OBJD], g_Wrp_l[HD * OBJD];
__device__ __half g_Wemb_h[HD * KEMB], g_Wemb_l[HD * KEMB];
__device__ __half g_Wcb_h[3 * HD * HD], g_Wcb_l[3 * HD * HD];
__device__ __half g_Wct_h[3 * HD * HD], g_Wct_l[3 * HD * HD];
__device__ __half g_Ugr2_h[HD * HD],   g_Ugr2_l[HD * HD];
__device__ __half g_Wgo_h[3 * HD * HD], g_Wgo_l[3 * HD * HD];
__device__ __half g_Ugo_h[3 * HD * HD], g_Ugo_l[3 * HD * HD];
__device__ __half g_Wcr_h[128 * HD], g_Wcr_l[128 * HD];
__device__ __half g_Wco_h[256 * HD], g_Wco_l[256 * HD];

// ============================================================================
// fp16 3-pass GEMM body (hi/lo planes), ldmatrix fragments.
// mode 0: C = A@B^T (+bias) (+addm); optional planes; packN>0 -> scalar pack.
// mode 1: GRU-fin fusion (contiguous XW3 only).
// ============================================================================
#define HROW 20
#define HPLW (128 * HROW)
#define HSTW (4 * HPLW)
#define HG_SMEM (2 * HSTW * 4)

struct HGArgs {
    const __half *Ah, *Al, *Bh, *Bl;
    float* C; int ldc;
    int M, N, K;
    const float* bias;
    const float* addm;
    __half *Ch, *Cl;
    int mode;
    int packN;
    const float* XW3; int ldxw;
    const float* Z;
    float* Hh;
};

__device__ __forceinline__ void hgemm_body(const HGArgs& a, int blk) {
    extern __shared__ uint32_t sm[];
    const int tid = threadIdx.x;
    const int lane = tid & 31;
    const int warp = tid >> 5;
    const int wm = warp >> 2;
    const int wn = warp & 3;
    const int lr = lane >> 2;
    const int lc = lane & 3;
    const int nx = a.N >> 7;
    const int m0 = (blk / nx) * 128;
    const int n0 = (blk % nx) * 128;
    const int K = a.K;
    const int KT = K / 32;

    const uint32_t sbase = (uint32_t)__cvta_generic_to_shared(sm);
    const int aRowOff = (wm * 64 + (lane & 15)) * HROW + (lane >> 4) * 4;
    const int bRowOff = (wn * 32 + (lane & 7) + ((lane >> 4) << 3)) * HROW
                      + (((lane >> 3) & 1) * 4);

    const __half* Ah = a.Ah;
    const __half* Al = a.Al;
    const __half* Bh = a.Bh;
    const __half* Bl = a.Bl;

    auto load_stage = [&](int kt, int buf) {
        const int k0 = kt * 32;
        uint32_t sb = sbase + (uint32_t)(buf * HSTW * 4);
#pragma unroll
        for (int i = 0; i < 2; i++) {
            int cid = tid * 2 + i;
            int row = cid >> 2, ch = cid & 3;
            uint32_t d = sb + (uint32_t)((row * HROW + ch * 4) * 4);
            size_t src = (size_t)(m0 + row) * K + k0 + ch * 8;
            cp16(d, Ah + src);
            cp16(d + HPLW * 4, Al + src);
        }
#pragma unroll
        for (int i = 0; i < 2; i++) {
            int cid = tid * 2 + i;
            int row = cid >> 2, ch = cid & 3;
            uint32_t d = sb + (uint32_t)((2 * HPLW + row * HROW + ch * 4) * 4);
            size_t src = (size_t)(n0 + row) * K + k0 + ch * 8;
            cp16(d, Bh + src);
            cp16(d + HPLW * 4, Bl + src);
        }
        asm volatile("cp.async.commit_group;");
    };

    float acc[4][4][4];
#pragma unroll
    for (int i = 0; i < 4; i++)
#pragma unroll
        for (int j = 0; j < 4; j++)
#pragma unroll
            for (int l = 0; l < 4; l++) acc[i][j][l] = 0.f;

    load_stage(0, 0);
    if (KT > 1) load_stage(1, 1);
    asm volatile("cp.async.wait_group 1;");
    __syncthreads();

    for (int kt = 0; kt < KT; kt++) {
        const int cur = kt & 1;
        const uint32_t uA = sbase + (uint32_t)(cur * HSTW * 4);
        const uint32_t uB = uA + (uint32_t)(2 * HPLW * 4);

#pragma unroll
        for (int wc = 0; wc < 16; wc += 8) {
            uint32_t aH[4][4], aL[4][4], bH[4][2], bL[4][2];
#pragma unroll
            for (int mt = 0; mt < 4; mt++) {
                uint32_t ad = uA + (uint32_t)((aRowOff + mt * 16 * HROW + wc) * 4);
                LDSM_X4(aH[mt][0], aH[mt][1], aH[mt][2], aH[mt][3], ad);
                LDSM_X4(aL[mt][0], aL[mt][1], aL[mt][2], aL[mt][3], ad + HPLW * 4);
            }
#pragma unroll
            for (int pr = 0; pr < 2; pr++) {
                uint32_t bd = uB + (uint32_t)((bRowOff + pr * 16 * HROW + wc) * 4);
                LDSM_X4(bH[2 * pr][0], bH[2 * pr][1], bH[2 * pr + 1][0], bH[2 * pr + 1][1], bd);
                LDSM_X4(bL[2 * pr][0], bL[2 * pr][1], bL[2 * pr + 1][0], bL[2 * pr + 1][1],
                        bd + HPLW * 4);
            }
#pragma unroll
            for (int mt = 0; mt < 4; mt++)
#pragma unroll
                for (int nt = 0; nt < 4; nt++) {
                    mma_f16(acc[mt][nt], aH[mt], bH[nt]);
                    mma_f16(acc[mt][nt], aH[mt], bL[nt]);
                    mma_f16(acc[mt][nt], aL[mt], bH[nt]);
                }
        }
        __syncthreads();
        if (kt + 2 < KT) {
            load_stage(kt + 2, cur);
            asm volatile("cp.async.wait_group 1;");
        } else if (kt + 1 < KT) {
            asm volatile("cp.async.wait_group 0;");
        }
        __syncthreads();
    }

    if (a.mode == 0) {
        if (a.packN > 0) {
#pragma unroll
            for (int mt = 0; mt < 4; mt++) {
#pragma unroll
                for (int nt = 0; nt < 4; nt++) {
#pragma unroll
                    for (int v = 0; v < 4; v++) {
                        int gm = m0 + wm * 64 + mt * 16 + lr + (v >> 1) * 8;
                        int gn = n0 + wn * 32 + nt * 8 + lc * 2 + (v & 1);
                        if (gn < a.packN)
                            a.C[(size_t)gm * a.ldc + gn] = acc[mt][nt][v] + a.bias[gn];
                    }
                }
            }
        } else {
#pragma unroll
            for (int mt = 0; mt < 4; mt++) {
                int gm0 = m0 + wm * 64 + mt * 16 + lr;
                int gm1 = gm0 + 8;
#pragma unroll
                for (int nt = 0; nt < 4; nt++) {
                    int gn = n0 + wn * 32 + nt * 8 + lc * 2;
                    float b0 = 0.f, b1 = 0.f;
                    if (a.bias) { b0 = a.bias[gn]; b1 = a.bias[gn + 1]; }
                    float2 v0 = make_float2(acc[mt][nt][0] + b0, acc[mt][nt][1] + b1);
                    float2 v1 = make_float2(acc[mt][nt][2] + b0, acc[mt][nt][3] + b1);
                    if (a.addm) {
                        float2 m0v = *(const float2*)(a.addm + (size_t)gm0 * a.ldc + gn);
                        float2 m1v = *(const float2*)(a.addm + (size_t)gm1 * a.ldc + gn);
                        v0.x += m0v.x; v0.y += m0v.y;
                        v1.x += m1v.x; v1.y += m1v.y;
                    }
                    *(float2*)(a.C + (size_t)gm0 * a.ldc + gn) = v0;
                    *(float2*)(a.C + (size_t)gm1 * a.ldc + gn) = v1;
                    if (a.Ch) {
                        __half hx, lx, hy, ly;
                        split_h(v0.x, hx, lx); split_h(v0.y, hy, ly);
                        *(__half2*)(a.Ch + (size_t)gm0 * a.ldc + gn) = __halves2half2(hx, hy);
                        *(__half2*)(a.Cl + (size_t)gm0 * a.ldc + gn) = __halves2half2(lx, ly);
                        split_h(v1.x, hx, lx); split_h(v1.y, hy, ly);
                        *(__half2*)(a.Ch + (size_t)gm1 * a.ldc + gn) = __halves2half2(hx, hy);
                        *(__half2*)(a.Cl + (size_t)gm1 * a.ldc + gn) = __halves2half2(lx, ly);
                    }
                }
            }
        }
    } else {
        // GRU-fin: n = tanh(acc + XW3 + b); h = (1-z)h + z n
#pragma unroll
        for (int mt = 0; mt < 4; mt++) {
#pragma unroll
            for (int nt = 0; nt < 4; nt++) {
#pragma unroll
                for (int v = 0; v < 4; v++) {
                    int gm = m0 + wm * 64 + mt * 16 + lr + (v >> 1) * 8;
                    int gn = n0 + wn * 32 + nt * 8 + lc * 2 + (v & 1);
                    size_t off = (size_t)gm * a.ldc + gn;
                    float n = tanhf(acc[mt][nt][v] + a.XW3[(size_t)gm * a.ldxw + gn]
                                    + a.bias[gn]);
                    float z = a.Z[off];
                    float h = (1.f - z) * a.Hh[off] + z * n;
                    a.Hh[off] = h;
                    __half ph, pl;
                    split_h(h, ph, pl);
                    a.Ch[off] = ph;
                    a.Cl[off] = pl;
                }
            }
        }
    }
}

__global__ __launch_bounds__(256, 2) void hgemm_kernel(HGArgs a) {
    hgemm_body(a, blockIdx.x);
}
__global__ __launch_bounds__(256, 2) void hgemm_dual_kernel(HGArgs a, HGArgs b, int na) {
    int bx = blockIdx.x;
    if (bx < na) hgemm_body(a, bx);
    else hgemm_body(b, bx - na);
}
__global__ __launch_bounds__(256, 2) void hgemm_tri_kernel(HGArgs a, HGArgs b, HGArgs c,
                                                           int na, int nab) {
    int bx = blockIdx.x;
    if (bx < na) hgemm_body(a, bx);
    else if (bx < nab) hgemm_body(b, bx - na);
    else hgemm_body(c, bx - nab);
}

// ---------------- split kernels ---------------------------------------------
// two-segment activation split (obj_fmaps then vr)
__global__ void asplit2_kernel(const float2* __restrict__ inA, __half2* __restrict__ hiA,
                               __half2* __restrict__ loA, int n2A,
                               const float2* __restrict__ inB, __half2* __restrict__ hiB,
                               __half2* __restrict__ loB, int n2B) {
    int i = blockIdx.x * blockDim.x + threadIdx.x;
    const float2* in;
    __half2 *hi, *lo;
    if (i < n2A) { in = inA + i; hi = hiA + i; lo = loA + i; }
    else {
        i -= n2A;
        if (i >= n2B) return;
        in = inB + i; hi = hiB + i; lo = loB + i;
    }
    float2 v = *in;
    __half hx, lx, hy, ly;
    split_h(v.x, hx, lx);
    split_h(v.y, hy, ly);
    *hi = __halves2half2(hx, hy);
    *lo = __halves2half2(lx, ly);
}

__global__ void wsplit_kernel(const float* __restrict__ W, int ldw, int c0, int wcols, int wrows,
                              __half* __restrict__ Th, __half* __restrict__ Tl, int K) {
    __shared__ float t[32][33];
    int kb = blockIdx.y * 32, nb = blockIdx.x * 32;
    int tx = threadIdx.x, ty = threadIdx.y;
    int col = c0 + nb + tx;
#pragma unroll
    for (int i = 0; i < 32; i += 8) {
        int kr = kb + ty + i;
        t[ty + i][tx] = (col < wcols && kr < wrows) ? W[(size_t)kr * ldw + col] : 0.f;
    }
    __syncthreads();
#pragma unroll
    for (int i = 0; i < 32; i += 8) {
        int n = nb + ty + i, k = kb + tx;
        __half h, l;
        split_h(t[tx][ty + i], h, l);
        Th[(size_t)n * K + k] = h;
        Tl[(size_t)n * K + k] = l;
    }
}

__global__ void biaspad_kernel(const float* __restrict__ b, float* __restrict__ out,
                               int n, int npad) {
    int i = blockIdx.x * blockDim.x + threadIdx.x;
    if (i < npad) out[i] = (i < n) ? b[i] : 0.f;
}

// ---------------- generic fp32 SGEMM (WCOMB only) -----------------------------
__global__ __launch_bounds__(256) void sgemm_kernel(
    const float* __restrict__ A, int lda,
    const float* __restrict__ B, int ldb,
    float* __restrict__ C, int ldc,
    int M, int N, int K)
{
    __shared__ float As[8][132];
    __shared__ float Bs[8][128];
    const int tid = threadIdx.x;
    const int tx = tid & 15;
    const int ty = tid >> 4;
    const int m0 = blockIdx.y * 128;
    const int n0 = blockIdx.x * 128;

    float acc[8][8];
#pragma unroll
    for (int i = 0; i < 8; i++)
#pragma unroll
        for (int j = 0; j < 8; j++) acc[i][j] = 0.f;

    for (int k0 = 0; k0 < K; k0 += 8) {
#pragma unroll
        for (int l = 0; l < 4; l++) {
            int e = tid + l * 256;
            int r = e >> 3, c = e & 7;
            float v = 0.f;
            int gm = m0 + r, gk = k0 + c;
            if (gm < M && gk < K) v = A[(size_t)gm * lda + gk];
            As[c][r] = v;
        }
#pragma unroll
        for (int l = 0; l < 4; l++) {
            int e = tid + l * 256;
            int r = e >> 7, c = e & 127;
            float v = 0.f;
            int gk = k0 + r, gn = n0 + c;
            if (gk < K && gn < N) v = B[(size_t)gk * ldb + gn];
            Bs[r][c] = v;
        }
        __syncthreads();
#pragma unroll
        for (int k = 0; k < 8; k++) {
            float a[8], b[8];
#pragma unroll
            for (int i = 0; i < 8; i++) a[i] = As[k][ty * 8 + i];
#pragma unroll
            for (int j = 0; j < 8; j++) b[j] = Bs[k][tx * 8 + j];
#pragma unroll
            for (int i = 0; i < 8; i++)
#pragma unroll
                for (int j = 0; j < 8; j++)
                    acc[i][j] = fmaf(a[i], b[j], acc[i][j]);
        }
        __syncthreads();
    }
#pragma unroll
    for (int i = 0; i < 8; i++) {
        int gm = m0 + ty * 8 + i;
        if (gm >= M) continue;
#pragma unroll
        for (int j = 0; j < 8; j++) {
            int gn = n0 + tx * 8 + j;
            if (gn >= N) continue;
            C[(size_t)gm * ldc + gn] = acc[i][j];
        }
    }
}

// ---------------- decode rel_inds --------------------------------------------
__global__ __launch_bounds__(1024) void decode_rel_kernel(const void* rel_raw) {
    __shared__ int s_or;
    int tid = threadIdx.x;
    if (tid == 0) s_or = 0;
    __syncthreads();
    const int* v32 = (const int*)rel_raw;
    int acc = 0;
    for (int i = tid; i < (3 * RR) / 2; i += 1024) acc |= v32[2 * i + 1];
    if (acc) atomicOr(&s_or, 1);
    __syncthreads();
    bool is64 = (s_or == 0);
    if (is64) {
        const long long* v = (const long long*)rel_raw;
        for (int r = tid; r < RR; r += 1024) {
            g_s_idx[r] = (int)v[3 * r + 1];
            g_o_idx[r] = (int)v[3 * r + 2];
        }
    } else {
        for (int r = tid; r < RR; r += 1024) {
            g_s_idx[r] = v32[3 * r + 1];
            g_o_idx[r] = v32[3 * r + 2];
        }
    }
}

// ---------------- per-object adjacency (deterministic order) ------------------
__global__ void build_adj_kernel() {
    int obj = blockIdx.x * blockDim.x + threadIdx.x;
    if (obj >= NN) return;
    int img = obj >> 6;
    int base = img * RPI_;
    int* lst = g_adj + (size_t)obj * 2 * RPI_;
    int cnt = 0;
    for (int j = 0; j < RPI_; j++) {
        int rel = base + j;
        if (g_s_idx[rel] == obj) lst[cnt++] = rel;
        if (g_o_idx[rel] == obj) lst[cnt++] = rel;
    }
    g_adj_cnt[obj] = cnt;
}

// ---------------- softmax -> padded fp16 planes -------------------------------
__global__ void softmax_split_kernel(const float* __restrict__ X,
                                     __half* __restrict__ Ph, __half* __restrict__ Pl) {
    int row = blockIdx.x;
    int tid = threadIdx.x;
    __shared__ float red[256];
    const float* x = X + (size_t)row * NOC_;
    float m = -3.4e38f;
    for (int c = tid; c < NOC_; c += 256) m = fmaxf(m, x[c]);
    red[tid] = m; __syncthreads();
    for (int s = 128; s > 0; s >>= 1) {
        if (tid < s) red[tid] = fmaxf(red[tid], red[tid + s]);
        __syncthreads();
    }
    m = red[0]; __syncthreads();
    float sum = 0.f;
    for (int c = tid; c < NOC_; c += 256) sum += expf(x[c] - m);
    red[tid] = sum; __syncthreads();
    for (int s = 128; s > 0; s >>= 1) {
        if (tid < s) red[tid] += red[tid + s];
        __syncthreads();
    }
    float inv = 1.f / red[0];
    for (int c = tid; c < KEMB; c += 256) {
        float v = (c < NOC_) ? expf(x[c] - m) * inv : 0.f;
        __half h, l;
        split_h(v, h, l);
        Ph[(size_t)row * KEMB + c] = h;
        Pl[(size_t)row * KEMB + c] = l;
    }
}

__global__ void softmax_kernel(const float* __restrict__ X, float* __restrict__ Y) {
    int row = blockIdx.x;
    int tid = threadIdx.x;
    __shared__ float red[256];
    const float* x = X + (size_t)row * NOC_;
    float m = -3.4e38f;
    for (int c = tid; c < NOC_; c += 256) m = fmaxf(m, x[c]);
    red[tid] = m; __syncthreads();
    for (int s = 128; s > 0; s >>= 1) {
        if (tid < s) red[tid] = fmaxf(red[tid], red[tid + s]);
        __syncthreads();
    }
    m = red[0]; __syncthreads();
    float sum = 0.f;
    for (int c = tid; c < NOC_; c += 256) sum += expf(x[c] - m);
    red[tid] = sum; __syncthreads();
    for (int s = 128; s > 0; s >>= 1) {
        if (tid < s) red[tid] += red[tid + s];
        __syncthreads();
    }
    float inv = 1.f / red[0];
    for (int c = tid; c < NOC_; c += 256)
        Y[(size_t)row * NOC_ + c] = expf(x[c] - m) * inv;
}

// ---------------- fused rel zr + n-part gather ---------------------------------
// z = (HW[s][c]+HW[o][c]) + HU_z + b_z ; r likewise; XWR3[row][c] = HW[s][1024+c]+HW[o][1024+c]
__global__ void rel_zr_kernel(const float* __restrict__ HW,
                              const float* __restrict__ HMHU,
                              const float* __restrict__ b, const float* __restrict__ Hh,
                              float* __restrict__ Z,
                              __half* __restrict__ RHh, __half* __restrict__ RHl,
                              float* __restrict__ XWR3) {
    int idx = blockIdx.x * blockDim.x + threadIdx.x;
    if (idx >= RR * HD) return;
    int row = idx >> 9;
    int c = idx & 511;
    int s = g_s_idx[row], o = g_o_idx[row];
    const float* hs = HW + (size_t)s * 1536;
    const float* ho = HW + (size_t)o * 1536;
    float xz = hs[c] + ho[c];
    float xr = hs[512 + c] + ho[512 + c];
    float xn = hs[1024 + c] + ho[1024 + c];
    const float* hu = HMHU + (size_t)row * 1536 + 512;
    float z = xz + hu[c] + b[c];
    float r = xr + hu[512 + c] + b[512 + c];
    z = 1.f / (1.f + expf(-z));
    r = 1.f / (1.f + expf(-r));
    Z[idx] = z;
    __half h, l;
    split_h(r * Hh[idx], h, l);
    RHh[idx] = h; RHl[idx] = l;
    XWR3[idx] = xn;
}

// ---------------- m_obj scatter via adjacency lists ---------------------------
__global__ __launch_bounds__(512) void scatter_obj_kernel(const float* __restrict__ HM, int ldhm,
                                                          __half* __restrict__ Mh,
                                                          __half* __restrict__ Ml) {
    int obj = blockIdx.x;
    int c = threadIdx.x;
    int cnt = g_adj_cnt[obj];
    const int* lst = g_adj + (size_t)obj * 2 * RPI_;
    float acc = 0.f;
    for (int k = 0; k < cnt; k++) {
        int rel = __ldg(lst + k);
        acc += HM[(size_t)rel * ldhm + c];
    }
    __half h, l;
    split_h(acc, h, l);
    Mh[(size_t)obj * HD + c] = h;
    Ml[(size_t)obj * HD + c] = l;
}

// ---------------- GRU z, r*h (obj path) ----------------------------------------
__global__ void gru_zr_kernel(const float* __restrict__ XW, int ldxw,
                              const float* __restrict__ HU, int ldhu,
                              const float* __restrict__ b, const float* __restrict__ Hh,
                              float* __restrict__ Z,
                              __half* __restrict__ RHh, __half* __restrict__ RHl, int M) {
    int idx = blockIdx.x * blockDim.x + threadIdx.x;
    if (idx >= M * HD) return;
    int row = idx >> 9;
    int c = idx & 511;
    float z = XW[(size_t)row * ldxw + c] + HU[(size_t)row * ldhu + c] + b[c];
    float r = XW[(size_t)row * ldxw + 512 + c] + HU[(size_t)row * ldhu + 512 + c] + b[512 + c];
    z = 1.f / (1.f + expf(-z));
    r = 1.f / (1.f + expf(-r));
    Z[idx] = z;
    __half h, l;
    split_h(r * Hh[idx], h, l);
    RHh[idx] = h; RHl[idx] = l;
}

// ---------------- NMS ----------------------------------------------------------
__global__ __launch_bounds__(512) void nms_kernel(const float* __restrict__ SP,
                                                  const float* __restrict__ BOX,
                                                  unsigned char* __restrict__ KEEP) {
    int cls = blockIdx.x + 1;
    int tid = threadIdx.x;
    __shared__ float sc[NN];
    __shared__ int sidx[NN];
    __shared__ float bx[NN][4];
    __shared__ float area[NN];
    __shared__ unsigned char keep[NN];

    sc[tid] = SP[(size_t)tid * NOC_ + cls];
    sidx[tid] = tid;
    __syncthreads();

    for (int k = 2; k <= NN; k <<= 1) {
        for (int j = k >> 1; j > 0; j >>= 1) {
            int ixj = tid ^ j;
            if (ixj > tid) {
                float s1 = sc[tid], s2 = sc[ixj];
                int i1 = sidx[tid], i2 = sidx[ixj];
                bool dir = ((tid & k) == 0);
                bool precBA = (s2 > s1) || (s2 == s1 && i2 < i1);
                if (precBA == dir) {
                    sc[tid] = s2; sc[ixj] = s1;
                    sidx[tid] = i2; sidx[ixj] = i1;
                }
            }
            __syncthreads();
        }
    }

    int oi = sidx[tid];
    float x1 = BOX[((size_t)oi * NOC_ + cls) * 4 + 0];
    float y1 = BOX[((size_t)oi * NOC_ + cls) * 4 + 1];
    float x2 = BOX[((size_t)oi * NOC_ + cls) * 4 + 2];
    float y2 = BOX[((size_t)oi * NOC_ + cls) * 4 + 3];
    bx[tid][0] = x1; bx[tid][1] = y1; bx[tid][2] = x2; bx[tid][3] = y2;
    area[tid] = (x2 - x1) * (y2 - y1);
    keep[tid] = 1;
    __syncthreads();

    for (int i = 0; i < NN - 1; i++) {
        if (tid > i && keep[i] && keep[tid]) {
            float lx = fmaxf(bx[i][0], x1);
            float ly = fmaxf(bx[i][1], y1);
            float rx = fminf(bx[i][2], x2);
            float ry = fminf(bx[i][3], y2);
            float w = fmaxf(rx - lx, 0.f);
            float h = fmaxf(ry - ly, 0.f);
            float inter = w * h;
            float iou = inter / (area[i] + area[tid] - inter + 1e-9f);
            if (iou > IOU_THR_) keep[tid] = 0;
        }
        __syncthreads();
    }
    KEEP[(size_t)(cls - 1) * NN + oi] = keep[tid];
}

// ---------------- obj_preds -----------------------------------------------------
__global__ void preds_kernel(const float* __restrict__ SP, const unsigned char* __restrict__ KEEP,
                             float* __restrict__ out) {
    int n = blockIdx.x * blockDim.x + threadIdx.x;
    if (n >= NN) return;
    float best = -1.f;
    int bi = 0;
    for (int c = 0; c < 150; c++) {
        float v = KEEP[(size_t)c * NN + n] ? SP[(size_t)n * NOC_ + c + 1] : 0.f;
        if (v > best) { best = v; bi = c; }
    }
    out[n] = (float)(bi + 1);
}

// ---------------- host orchestration --------------------------------------------
struct Scratch {
    float *FO, *HOBJ, *HREL, *XWR3, *HMHU, *HW, *ZR;
    float *XWO, *HUO, *ZO, *SP, *WCOMB, *BCR, *BCO;
    unsigned char* KEEP;
    __half *Pa_h, *Pa_l, *Pb_h, *Pb_l, *Ps_h, *Ps_l, *Ph_h, *Ph_l;
    __half *Po1_h, *Po1_l, *Po2_h, *Po2_l, *Po3_h, *Po3_l, *OP_h, *OP_l;
    __half *Wop_h, *Wop_l, *Wrp_h, *Wrp_l, *Wemb_h, *Wemb_l;
    __half *Wcb_h, *Wcb_l, *Wct_h, *Wct_l;
    __half *Ugr2_h, *Ugr2_l, *Wgo_h, *Wgo_l, *Ugo_h, *Ugo_l;
    __half *Wcr_h, *Wcr_l, *Wco_h, *Wco_l;
    bool init = false;
};
static Scratch g_sc;

static void init_scratch() {
    if (g_sc.init) return;
    void* p;
#define GET(sym, fld, T) cudaGetSymbolAddress(&p, sym); g_sc.fld = (T*)p;
    GET(g_fo, FO, float)
    GET(g_h_obj, HOBJ, float)
    GET(g_h_rel, HREL, float)
    GET(g_xwr3, XWR3, float)
    GET(g_hmhu, HMHU, float)
    GET(g_hw, HW, float)
    GET(g_z_rel, ZR, float)
    GET(g_xw_obj, XWO, float)
    GET(g_hu_obj, HUO, float)
    GET(g_z_obj, ZO, float)
    GET(g_sp, SP, float)
    GET(g_wcomb, WCOMB, float)
    GET(g_bcr, BCR, float)
    GET(g_bco, BCO, float)
    GET(g_keep, KEEP, unsigned char)
    GET(g_Pa_h, Pa_h, __half) GET(g_Pa_l, Pa_l, __half)
    GET(g_Pb_h, Pb_h, __half) GET(g_Pb_l, Pb_l, __half)
    GET(g_Ps_h, Ps_h, __half) GET(g_Ps_l, Ps_l, __half)
    GET(g_Ph_h, Ph_h, __half) GET(g_Ph_l, Ph_l, __half)
    GET(g_Po1_h, Po1_h, __half) GET(g_Po1_l, Po1_l, __half)
    GET(g_Po2_h, Po2_h, __half) GET(g_Po2_l, Po2_l, __half)
    GET(g_Po3_h, Po3_h, __half) GET(g_Po3_l, Po3_l, __half)
    GET(g_OP_h, OP_h, __half)  GET(g_OP_l, OP_l, __half)
    GET(g_Wop_h, Wop_h, __half) GET(g_Wop_l, Wop_l, __half)
    GET(g_Wrp_h, Wrp_h, __half) GET(g_Wrp_l, Wrp_l, __half)
    GET(g_Wemb_h, Wemb_h, __half) GET(g_Wemb_l, Wemb_l, __half)
    GET(g_Wcb_h, Wcb_h, __half) GET(g_Wcb_l, Wcb_l, __half)
    GET(g_Wct_h, Wct_h, __half) GET(g_Wct_l, Wct_l, __half)
    GET(g_Ugr2_h, Ugr2_h, __half) GET(g_Ugr2_l, Ugr2_l, __half)
    GET(g_Wgo_h, Wgo_h, __half) GET(g_Wgo_l, Wgo_l, __half)
    GET(g_Ugo_h, Ugo_h, __half) GET(g_Ugo_l, Ugo_l, __half)
    GET(g_Wcr_h, Wcr_h, __half) GET(g_Wcr_l, Wcr_l, __half)
    GET(g_Wco_h, Wco_h, __half) GET(g_Wco_l, Wco_l, __half)
#undef GET
    cudaFuncSetAttribute(hgemm_kernel, cudaFuncAttributeMaxDynamicSharedMemorySize, HG_SMEM);
    cudaFuncSetAttribute(hgemm_dual_kernel, cudaFuncAttributeMaxDynamicSharedMemorySize, HG_SMEM);
    cudaFuncSetAttribute(hgemm_tri_kernel, cudaFuncAttributeMaxDynamicSharedMemorySize, HG_SMEM);
    g_sc.init = true;
}

static HGArgs mkargs(const __half* Ah, const __half* Al, const __half* Bh, const __half* Bl,
                     float* C, int ldc, int M, int N, int K, const float* bias,
                     __half* Ch = nullptr, __half* Cl = nullptr) {
    HGArgs a;
    a.Ah = Ah; a.Al = Al; a.Bh = Bh; a.Bl = Bl;
    a.C = C; a.ldc = ldc; a.M = M; a.N = N; a.K = K;
    a.bias = bias; a.addm = nullptr; a.Ch = Ch; a.Cl = Cl;
    a.mode = 0; a.packN = 0;
    a.XW3 = nullptr; a.ldxw = 0; a.Z = nullptr; a.Hh = nullptr;
    return a;
}

static int nblk(const HGArgs& a) { return (a.M / 128) * (a.N / 128); }
static void hgemm1(const HGArgs& a) {
    hgemm_kernel<<<nblk(a), 256, HG_SMEM>>>(a);
}
static void hgemm2(const HGArgs& a, const HGArgs& b) {
    hgemm_dual_kernel<<<nblk(a) + nblk(b), 256, HG_SMEM>>>(a, b, nblk(a));
}
static void hgemm3(const HGArgs& a, const HGArgs& b, const HGArgs& c) {
    int na = nblk(a), nab = na + nblk(b);
    hgemm_tri_kernel<<<nab + nblk(c), 256, HG_SMEM>>>(a, b, c, na, nab);
}

static void wsplit(const float* W, int ldw, int c0, int wcols, int wrows,
                   __half* Th, __half* Tl, int K, int ncols) {
    dim3 g(ncols / 32, K / 32);
    wsplit_kernel<<<g, dim3(32, 8)>>>(W, ldw, c0, wcols, wrows, Th, Tl, K);
}

extern "C" void kernel_launch(void* const* d_in, const int* in_sizes, int n_in,
                              void* d_out, int out_size) {
    (void)in_sizes; (void)n_in; (void)out_size;
    init_scratch();

    const float* obj_fmaps  = (const float*)d_in[1];
    const float* obj_logits = (const float*)d_in[2];
    const void*  rel_raw    = d_in[3];
    const float* vr         = (const float*)d_in[4];
    const float* boxes      = (const float*)d_in[5];
    const float* W_obj_proj = (const float*)d_in[6];
    const float* b_obj_proj = (const float*)d_in[7];
    const float* W_rel_proj = (const float*)d_in[8];
    const float* b_rel_proj = (const float*)d_in[9];
    const float* W_emb      = (const float*)d_in[10];
    const float* W_msg_rel  = (const float*)d_in[11];
    const float* W_msg_obj  = (const float*)d_in[12];
    const float* W_gru_obj  = (const float*)d_in[13];
    const float* U_gru_obj  = (const float*)d_in[14];
    const float* b_gru_obj  = (const float*)d_in[15];
    const float* W_gru_rel  = (const float*)d_in[16];
    const float* U_gru_rel  = (const float*)d_in[17];
    const float* b_gru_rel  = (const float*)d_in[18];
    const float* W_cls_rel  = (const float*)d_in[19];
    const float* b_cls_rel  = (const float*)d_in[20];
    const float* W_cls_obj  = (const float*)d_in[21];
    const float* b_cls_obj  = (const float*)d_in[22];

    float* out_obj_logits = (float*)d_out;
    float* out_preds      = out_obj_logits + NN * NOC_;
    float* out_rel_logits = out_preds + NN;

    // 0. decode + adjacency; weight planes
    decode_rel_kernel<<<1, 1024>>>(rel_raw);
    build_adj_kernel<<<2, 256>>>();
    wsplit(W_obj_proj, HD, 0, HD, OBJD, g_sc.Wop_h, g_sc.Wop_l, OBJD, HD);
    wsplit(W_rel_proj, HD, 0, HD, OBJD, g_sc.Wrp_h, g_sc.Wrp_l, OBJD, HD);
    wsplit(W_emb, HD, 0, HD, NOC_, g_sc.Wemb_h, g_sc.Wemb_l, KEMB, HD);
    wsplit(W_msg_obj, HD, 0, HD, HD, g_sc.Wct_h, g_sc.Wct_l, HD, HD);
    wsplit(U_gru_rel, 3 * HD, 0, 3 * HD, HD, g_sc.Wct_h + (size_t)HD * HD,
           g_sc.Wct_l + (size_t)HD * HD, HD, 2 * HD);
    wsplit(U_gru_rel, 3 * HD, 2 * HD, 3 * HD, HD, g_sc.Ugr2_h, g_sc.Ugr2_l, HD, HD);
    wsplit(W_gru_obj, 3 * HD, 0, 3 * HD, HD, g_sc.Wgo_h, g_sc.Wgo_l, HD, 3 * HD);
    wsplit(U_gru_obj, 3 * HD, 0, 3 * HD, HD, g_sc.Ugo_h, g_sc.Ugo_l, HD, 3 * HD);
    wsplit(W_cls_rel, NRC_, 0, NRC_, HD, g_sc.Wcr_h, g_sc.Wcr_l, HD, 128);
    wsplit(W_cls_obj, NOC_, 0, NOC_, HD, g_sc.Wco_h, g_sc.Wco_l, HD, 256);
    biaspad_kernel<<<1, 128>>>(b_cls_rel, g_sc.BCR, NRC_, 128);
    biaspad_kernel<<<1, 256>>>(b_cls_obj, g_sc.BCO, NOC_, 256);
    {
        dim3 g((3 * HD + 127) / 128, (HD + 127) / 128);
        sgemm_kernel<<<g, 256>>>(W_msg_rel, HD, W_gru_rel, 3 * HD, g_sc.WCOMB, 3 * HD,
                                 HD, 3 * HD, HD);
    }
    wsplit(g_sc.WCOMB, 3 * HD, 0, 3 * HD, HD, g_sc.Wcb_h, g_sc.Wcb_l, HD, 3 * HD);

    // 1. activation splits (obj_fmaps + vr in one launch) + softmax planes
    {
        int n2A = NN * OBJD / 2, n2B = RR * OBJD / 2;
        asplit2_kernel<<<(n2A + n2B + 255) / 256, 256>>>(
            (const float2*)obj_fmaps, (__half2*)g_sc.Pb_h, (__half2*)g_sc.Pb_l, n2A,
            (const float2*)vr, (__half2*)g_sc.Pa_h, (__half2*)g_sc.Pa_l, n2B);
    }
    softmax_split_kernel<<<NN, 256>>>(obj_logits, g_sc.OP_h, g_sc.OP_l);

    // 2. fo + h_rel (paired)
    hgemm2(mkargs(g_sc.Pb_h, g_sc.Pb_l, g_sc.Wop_h, g_sc.Wop_l, g_sc.FO, HD,
                  NN, HD, OBJD, b_obj_proj),
           mkargs(g_sc.Pa_h, g_sc.Pa_l, g_sc.Wrp_h, g_sc.Wrp_l, g_sc.HREL, HD,
                  RR, HD, OBJD, b_rel_proj, g_sc.Ph_h, g_sc.Ph_l));

    // 3. h_obj = obj_probs @ W_emb + fo
    {
        HGArgs a = mkargs(g_sc.OP_h, g_sc.OP_l, g_sc.Wemb_h, g_sc.Wemb_l, g_sc.HOBJ, HD,
                          NN, HD, KEMB, nullptr, g_sc.Po2_h, g_sc.Po2_l);
        a.addm = g_sc.FO;
        hgemm1(a);
    }

    const int EW_REL = (RR * HD + 255) / 256;
    const int EW_OBJ = (NN * HD + 255) / 256;
    const __half* Ugo2_h = g_sc.Ugo_h + (size_t)2 * HD * HD;
    const __half* Ugo2_l = g_sc.Ugo_l + (size_t)2 * HD * HD;

    for (int t = 0; t < TSTEPS; t++) {
        // HW = HOBJ@WCOMB ; HMHU = h_rel@WCAT ; HUO = HOBJ@Ugo01  (one tri launch)
        hgemm3(mkargs(g_sc.Po2_h, g_sc.Po2_l, g_sc.Wcb_h, g_sc.Wcb_l, g_sc.HW, 3 * HD,
                      NN, 3 * HD, HD, nullptr),
               mkargs(g_sc.Ph_h, g_sc.Ph_l, g_sc.Wct_h, g_sc.Wct_l, g_sc.HMHU, 3 * HD,
                      RR, 3 * HD, HD, nullptr),
               mkargs(g_sc.Po2_h, g_sc.Po2_l, g_sc.Ugo_h, g_sc.Ugo_l, g_sc.HUO, 2 * HD,
                      NN, 2 * HD, HD, nullptr));
        // fused: rel zr gates (gathered from HW) + compact n-part XWR3
        rel_zr_kernel<<<EW_REL, 256>>>(g_sc.HW, g_sc.HMHU, b_gru_rel, g_sc.HREL,
                                       g_sc.ZR, g_sc.Ps_h, g_sc.Ps_l, g_sc.XWR3);
        scatter_obj_kernel<<<NN, 512>>>(g_sc.HMHU, 3 * HD, g_sc.Po1_h, g_sc.Po1_l);

        // (rel NU+fin) paired with XWO
        {
            HGArgs fin = mkargs(g_sc.Ps_h, g_sc.Ps_l, g_sc.Ugr2_h, g_sc.Ugr2_l,
                                nullptr, HD, RR, HD, HD, b_gru_rel + 2 * HD,
                                g_sc.Ph_h, g_sc.Ph_l);
            fin.mode = 1; fin.XW3 = g_sc.XWR3; fin.ldxw = HD;
            fin.Z = g_sc.ZR; fin.Hh = g_sc.HREL;
            hgemm2(fin,
                   mkargs(g_sc.Po1_h, g_sc.Po1_l, g_sc.Wgo_h, g_sc.Wgo_l, g_sc.XWO, 3 * HD,
                          NN, 3 * HD, HD, nullptr));
        }

        // GRU obj zr; NU+fin
        gru_zr_kernel<<<EW_OBJ, 256>>>(g_sc.XWO, 3 * HD, g_sc.HUO, 2 * HD,
                                       b_gru_obj, g_sc.HOBJ, g_sc.ZO, g_sc.Po3_h, g_sc.Po3_l, NN);
        {
            HGArgs fin = mkargs(g_sc.Po3_h, g_sc.Po3_l, Ugo2_h, Ugo2_l,
                                nullptr, HD, NN, HD, HD, b_gru_obj + 2 * HD,
                                g_sc.Po2_h, g_sc.Po2_l);
            fin.mode = 1; fin.XW3 = g_sc.XWO + 2 * HD; fin.ldxw = 3 * HD;
            fin.Z = g_sc.ZO; fin.Hh = g_sc.HOBJ;
            hgemm1(fin);
        }
    }

    // classifiers write straight into d_out (packN scalar stores)
    {
        HGArgs rc = mkargs(g_sc.Ph_h, g_sc.Ph_l, g_sc.Wcr_h, g_sc.Wcr_l,
                           out_rel_logits, NRC_, RR, 128, HD, g_sc.BCR);
        rc.packN = NRC_;
        HGArgs oc = mkargs(g_sc.Po2_h, g_sc.Po2_l, g_sc.Wco_h, g_sc.Wco_l,
                           out_obj_logits, NOC_, NN, 256, HD, g_sc.BCO);
        oc.packN = NOC_;
        hgemm2(rc, oc);
    }

    // softmax -> NMS -> preds
    softmax_kernel<<<NN, 256>>>(out_obj_logits, g_sc.SP);
    nms_kernel<<<150, 512>>>(g_sc.SP, boxes, g_sc.KEEP);
    preds_kernel<<<(NN + 255) / 256, 256>>>(g_sc.SP, g_sc.KEEP, out_preds);
}